// round 4
// baseline (speedup 1.0000x reference)
#include <cuda_runtime.h>
#include <cuda_bf16.h>
#include <math.h>

#define BB 128
#define LL 512
#define LAa 8
#define EE 300
#define HH 300
#define G3 900

__device__ __align__(16) int   g_mem_len[BB];
__device__ __align__(16) int   g_asp_len[BB];
__device__ __align__(16) int   g_left_len[BB];
__device__ __align__(16) int   g_right_len[BB];
__device__ __align__(16) int   g_order_l[BB];
__device__ __align__(16) int   g_order_r[BB];
__device__ __align__(16) float g_qdot[BB];
__device__ __align__(16) float g_attn_l[BB * LL];
__device__ __align__(16) float g_attn_r[BB * LL];
__device__ __align__(16) float g_Wt_l[HH * G3];   // Wt[k*900+g] = Whh[g*300+k]
__device__ __align__(16) float g_Wt_r[HH * G3];
__device__ __align__(16) float g_xp_l[(size_t)BB * LL * G3];
__device__ __align__(16) float g_xp_r[(size_t)BB * LL * G3];
__device__ __align__(16) float g_memory[(size_t)BB * LL * EE];
__device__ __align__(16) float g_kx[(size_t)BB * LL * EE];
__device__ __align__(16) float g_vs[BB * EE];

__device__ __forceinline__ float sigf(float x) { return 1.0f / (1.0f + expf(-x)); }

// ---------------- K_wt: transpose both W_hh into gate-major layout ------------
__global__ void k_wt(const float* __restrict__ Whh_l, const float* __restrict__ Whh_r)
{
    int g = blockIdx.x, side = blockIdx.y, k = threadIdx.x;  // k in [0,300)
    const float* W = side ? Whh_r : Whh_l;
    float* Wt = side ? g_Wt_r : g_Wt_l;
    Wt[(size_t)k * G3 + g] = W[(size_t)g * HH + k];
}

// ---------------- K0: lengths, attn defaults, aspect mean -> qdot -------------
__global__ void k_init(const int* __restrict__ text, const int* __restrict__ aspi,
                       const int* __restrict__ xl, const int* __restrict__ xr,
                       const float* __restrict__ emb_aspect,
                       const float* __restrict__ w_q, const float* __restrict__ b_q,
                       const float* __restrict__ attn_w,
                       const float* __restrict__ mlp_l_b, const float* __restrict__ mlp_r_b)
{
    int b = blockIdx.x, tid = threadIdx.x;
    int ml = __syncthreads_count(text[b * LL + tid] != 0);
    int ll = __syncthreads_count(xl[b * LL + tid] != 0);
    int rl = __syncthreads_count(xr[b * LL + tid] != 0);
    int al = __syncthreads_count((tid < LAa) && (aspi[b * LAa + tid] != 0));
    if (tid == 0) { g_mem_len[b] = ml; g_left_len[b] = ll; g_right_len[b] = rl; g_asp_len[b] = al; }
    g_attn_l[b * LL + tid] = sigf(mlp_l_b[0]) + 0.5f;
    g_attn_r[b * LL + tid] = sigf(mlp_r_b[0]) + 0.5f;

    __shared__ float s_asp[EE];
    __shared__ float sred[16];
    if (tid < EE) {
        float acc = 0.f;
        #pragma unroll
        for (int a = 0; a < LAa; a++)
            if (a < al) acc += emb_aspect[(size_t)aspi[b * LAa + a] * EE + tid];
        s_asp[tid] = acc / (float)al;
    }
    __syncthreads();
    float val = 0.f;
    if (tid < EE) {
        float acc = b_q[tid];
        const float* wq = w_q + (size_t)tid * EE;
        for (int e = 0; e < EE; e++) acc += s_asp[e] * wq[e];
        val = acc * attn_w[EE + tid];
    }
    #pragma unroll
    for (int o = 16; o > 0; o >>= 1) val += __shfl_xor_sync(0xffffffffu, val, o);
    if ((tid & 31) == 0) sred[tid >> 5] = val;
    __syncthreads();
    if (tid == 0) {
        float s = 0.f;
        #pragma unroll
        for (int w = 0; w < 16; w++) s += sred[w];
        g_qdot[b] = s;
    }
}

// ---------------- K_sort: rank-sort sequence lengths (desc) per side ----------
__global__ void k_sort()
{
    int tid = threadIdx.x;            // 256 threads
    int side = tid >> 7, i = tid & 127;
    const int* lens = side ? g_right_len : g_left_len;
    int* ord = side ? g_order_r : g_order_l;
    int li = lens[i], r = 0;
    for (int j = 0; j < BB; j++) {
        int lj = lens[j];
        r += (lj > li) || (lj == li && j < i);
    }
    ord[r] = i;
}

// ---------------- K1: tiled fp32 GEMM (unchanged from passing version) --------
__global__ void __launch_bounds__(256) k_gemm(
    const float* __restrict__ Aext, const int* __restrict__ ids,
    const float* __restrict__ W, const float* __restrict__ bias,
    int N, int dst_sel, int limit_sel)
{
    const int K = EE;
    int b = blockIdx.z, m0 = blockIdx.y * 64, n0 = blockIdx.x * 64;
    int lim = (limit_sel == 1) ? g_left_len[b] : (limit_sel == 2) ? g_right_len[b] : LL;
    if (m0 >= lim) return;

    float* C = (dst_sel == 0) ? g_xp_l : (dst_sel == 1) ? g_xp_r : g_kx;
    float* Cb = C + (size_t)b * LL * N;
    const int* bids = ids ? (ids + (size_t)b * LL) : (const int*)0;

    __shared__ float As[16][64];
    __shared__ float Bs[16][64];

    int tid = threadIdx.x;
    int tx = tid & 15, ty = tid >> 4;
    int lrow = tid >> 2, lc4 = (tid & 3) << 2;

    int gm = m0 + lrow;
    const float* arow;
    if (bids) arow = Aext + (size_t)bids[gm] * K;
    else      arow = g_memory + ((size_t)b * LL + gm) * K;
    int gn = n0 + lrow;
    const float* brow = (gn < N) ? (W + (size_t)gn * K) : (const float*)0;

    float acc[4][4];
    #pragma unroll
    for (int i = 0; i < 4; i++)
        #pragma unroll
        for (int j = 0; j < 4; j++) acc[i][j] = 0.f;

    for (int k0 = 0; k0 < K; k0 += 16) {
        float4 av = make_float4(0.f, 0.f, 0.f, 0.f);
        float4 bv = make_float4(0.f, 0.f, 0.f, 0.f);
        if (k0 + lc4 < K) {
            av = *(const float4*)(arow + k0 + lc4);
            if (brow) bv = *(const float4*)(brow + k0 + lc4);
        }
        __syncthreads();
        As[lc4 + 0][lrow] = av.x; As[lc4 + 1][lrow] = av.y;
        As[lc4 + 2][lrow] = av.z; As[lc4 + 3][lrow] = av.w;
        Bs[lc4 + 0][lrow] = bv.x; Bs[lc4 + 1][lrow] = bv.y;
        Bs[lc4 + 2][lrow] = bv.z; Bs[lc4 + 3][lrow] = bv.w;
        __syncthreads();
        #pragma unroll
        for (int kk = 0; kk < 16; kk++) {
            float4 a  = *(const float4*)&As[kk][ty << 2];
            float4 bb = *(const float4*)&Bs[kk][tx << 2];
            acc[0][0] += a.x * bb.x; acc[0][1] += a.x * bb.y; acc[0][2] += a.x * bb.z; acc[0][3] += a.x * bb.w;
            acc[1][0] += a.y * bb.x; acc[1][1] += a.y * bb.y; acc[1][2] += a.y * bb.z; acc[1][3] += a.y * bb.w;
            acc[2][0] += a.z * bb.x; acc[2][1] += a.z * bb.y; acc[2][2] += a.z * bb.z; acc[2][3] += a.z * bb.w;
            acc[3][0] += a.w * bb.x; acc[3][1] += a.w * bb.y; acc[3][2] += a.w * bb.z; acc[3][3] += a.w * bb.w;
        }
    }
    #pragma unroll
    for (int i = 0; i < 4; i++) {
        int om = m0 + (ty << 2) + i;
        #pragma unroll
        for (int j = 0; j < 4; j++) {
            int on = n0 + (tx << 2) + j;
            if (on < N) Cb[(size_t)om * N + on] = acc[i][j] + bias[on];
        }
    }
}

// ---------------- K2: GRU v2 — coalesced transposed weights, sorted pairs -----
// 128 blocks x 320 threads. blocks 0..63 left, 64..127 right.
// Block pb handles seqs order[2pb] (A, longer) and order[2pb+1] (B).
// Phase A: threads 0..224 each compute 4 gate outputs (coalesced float4 W reads).
// Phase B: threads 0..299 update h and reduce attn scalar.
__global__ void __launch_bounds__(320) k_gru2(
    const float* __restrict__ bhh_l, const float* __restrict__ bhh_r,
    const float* __restrict__ mlpw_l, const float* __restrict__ mlpb_l,
    const float* __restrict__ mlpw_r, const float* __restrict__ mlpb_r)
{
    int side = (blockIdx.x >= 64);
    int pb = blockIdx.x & 63;
    const float* Wt   = side ? g_Wt_r : g_Wt_l;
    const float* bhh  = side ? bhh_r : bhh_l;
    const float* mlpw = side ? mlpw_r : mlpw_l;
    float mb          = side ? mlpb_r[0] : mlpb_l[0];
    const float* xp   = side ? g_xp_r : g_xp_l;
    const int* lens   = side ? g_right_len : g_left_len;
    const int* ord    = side ? g_order_r : g_order_l;
    float* attn       = side ? g_attn_r : g_attn_l;

    int sA = ord[2 * pb], sB = ord[2 * pb + 1];
    int lenA = lens[sA], lenB = lens[sB];    // lenA >= lenB by sort

    int tid = threadIdx.x, lane = tid & 31, wid = tid >> 5;

    __shared__ float2 s_h[EE];
    __shared__ float  s_gate[2][G3];
    __shared__ float  parts[2][10];

    float wm = 0.f, bhr = 0.f, bhz = 0.f, bhn = 0.f;
    if (tid < EE) {
        wm = mlpw[tid];
        bhr = bhh[tid]; bhz = bhh[HH + tid]; bhn = bhh[2 * HH + tid];
        s_h[tid] = make_float2(0.f, 0.f);
    }
    const float* xpA = xp + (size_t)sA * LL * G3;
    const float* xpB = xp + (size_t)sB * LL * G3;
    const float4* W4 = ((const float4*)Wt) + tid;   // valid when tid<225
    __syncthreads();

    for (int t = 0; t < lenA; t++) {
        bool aB = (t < lenB);
        // prefetch xp gate inputs (hidden under the FMA loop)
        float gA0 = 0.f, gA1 = 0.f, gA2 = 0.f, gB0 = 0.f, gB1 = 0.f, gB2 = 0.f;
        if (tid < EE) {
            const float* g = xpA + (size_t)t * G3;
            gA0 = g[tid]; gA1 = g[HH + tid]; gA2 = g[2 * HH + tid];
            if (aB) {
                const float* h = xpB + (size_t)t * G3;
                gB0 = h[tid]; gB1 = h[HH + tid]; gB2 = h[2 * HH + tid];
            }
        }
        // Phase A: gate GEMV, 4 gates per thread
        if (tid < 225) {
            float a0 = 0.f, a1 = 0.f, a2 = 0.f, a3 = 0.f;
            float b0 = 0.f, b1 = 0.f, b2 = 0.f, b3 = 0.f;
            if (aB) {
                #pragma unroll 4
                for (int k = 0; k < HH; k++) {
                    float4 w = W4[(size_t)k * 225];
                    float2 h = s_h[k];
                    a0 = fmaf(w.x, h.x, a0); a1 = fmaf(w.y, h.x, a1);
                    a2 = fmaf(w.z, h.x, a2); a3 = fmaf(w.w, h.x, a3);
                    b0 = fmaf(w.x, h.y, b0); b1 = fmaf(w.y, h.y, b1);
                    b2 = fmaf(w.z, h.y, b2); b3 = fmaf(w.w, h.y, b3);
                }
                *(float4*)&s_gate[1][tid * 4] = make_float4(b0, b1, b2, b3);
            } else {
                #pragma unroll 4
                for (int k = 0; k < HH; k++) {
                    float4 w = W4[(size_t)k * 225];
                    float hx = s_h[k].x;
                    a0 = fmaf(w.x, hx, a0); a1 = fmaf(w.y, hx, a1);
                    a2 = fmaf(w.z, hx, a2); a3 = fmaf(w.w, hx, a3);
                }
            }
            *(float4*)&s_gate[0][tid * 4] = make_float4(a0, a1, a2, a3);
        }
        __syncthreads();
        // Phase B: h update + attn partial
        float vA = 0.f, vB = 0.f;
        if (tid < EE) {
            float2 h = s_h[tid];
            {
                float r = sigf(gA0 + s_gate[0][tid] + bhr);
                float z = sigf(gA1 + s_gate[0][HH + tid] + bhz);
                float n = tanhf(gA2 + r * (s_gate[0][2 * HH + tid] + bhn));
                h.x = (1.f - z) * n + z * h.x;
                vA = h.x * wm;
            }
            if (aB) {
                float r = sigf(gB0 + s_gate[1][tid] + bhr);
                float z = sigf(gB1 + s_gate[1][HH + tid] + bhz);
                float n = tanhf(gB2 + r * (s_gate[1][2 * HH + tid] + bhn));
                h.y = (1.f - z) * n + z * h.y;
                vB = h.y * wm;
            }
            s_h[tid] = h;
        }
        #pragma unroll
        for (int o = 16; o > 0; o >>= 1) {
            vA += __shfl_xor_sync(0xffffffffu, vA, o);
            vB += __shfl_xor_sync(0xffffffffu, vB, o);
        }
        if (lane == 0) { parts[0][wid] = vA; parts[1][wid] = vB; }
        __syncthreads();
        if (tid == 0) {
            float s = 0.f;
            #pragma unroll
            for (int w = 0; w < 10; w++) s += parts[0][w];
            attn[sA * LL + t] = sigf(s + mb) + 0.5f;
        }
        if (tid == 1 && aB) {
            float s = 0.f;
            #pragma unroll
            for (int w = 0; w < 10; w++) s += parts[1][w];
            attn[sB * LL + t] = sigf(s + mb) + 0.5f;
        }
    }
}

// ---------------- K3: memory = emb[text] * scale ------------------------------
__global__ void k_mem(const int* __restrict__ text, const float* __restrict__ emb)
{
    int l = blockIdx.x, b = blockIdx.y, tid = threadIdx.x;
    if (tid >= EE) return;
    float* row = g_memory + ((size_t)b * LL + l) * EE;
    int ml = g_mem_len[b];
    if (l >= ml) { row[tid] = 0.f; return; }
    int astart = g_left_len[b] - g_asp_len[b];
    int aend = g_left_len[b];
    float al = g_attn_l[b * LL + l];
    int ridx = min(max(l - astart, 0), LL - 1);
    float arv = g_attn_r[b * LL + ridx];
    float sc = (l < astart) ? al : ((l < aend) ? (al + arv) : arv);
    int id = text[b * LL + l];
    row[tid] = emb[(size_t)id * EE + tid] * sc;
}

// ---------------- K4: v_s -----------------------------------------------------
__global__ void k_vs()
{
    int b = blockIdx.x, tid = threadIdx.x;
    if (tid >= EE) return;
    float acc = 0.f;
    const float* p = g_memory + (size_t)b * LL * EE + tid;
    for (int l = 0; l < LL; l++) acc += p[(size_t)l * EE];
    g_vs[b * EE + tid] = acc / (float)g_mem_len[b];
}

// ---------------- K5: score->softmax->v_ts->proj->mlp->dense ------------------
__global__ void __launch_bounds__(512) k_tail(
    const float* __restrict__ attn_w,
    const float* __restrict__ proj_w, const float* __restrict__ proj_b,
    const float* __restrict__ mlp_w, const float* __restrict__ mlp_b,
    const float* __restrict__ dense_w, const float* __restrict__ dense_b,
    float* __restrict__ out)
{
    int b = blockIdx.x, tid = threadIdx.x, lane = tid & 31, wid = tid >> 5;
    __shared__ float s_aw[EE];
    __shared__ float s_sc[LL];
    __shared__ float smax[16], ssum[16];
    __shared__ float s_v[EE], s_v2[EE];
    const float* kxb = g_kx + (size_t)b * LL * EE;
    if (tid < EE) s_aw[tid] = attn_w[tid];
    __syncthreads();
    float qd = g_qdot[b];
    for (int l = wid; l < LL; l += 16) {
        const float* row = kxb + (size_t)l * EE;
        float acc = 0.f;
        for (int e = lane; e < EE; e += 32) acc += row[e] * s_aw[e];
        #pragma unroll
        for (int o = 16; o > 0; o >>= 1) acc += __shfl_xor_sync(0xffffffffu, acc, o);
        if (lane == 0) s_sc[l] = tanhf(acc + qd);
    }
    __syncthreads();
    float x = s_sc[tid];
    float m = x;
    #pragma unroll
    for (int o = 16; o > 0; o >>= 1) m = fmaxf(m, __shfl_xor_sync(0xffffffffu, m, o));
    if (lane == 0) smax[wid] = m;
    __syncthreads();
    float bm = smax[0];
    #pragma unroll
    for (int w = 1; w < 16; w++) bm = fmaxf(bm, smax[w]);
    float p = expf(x - bm);
    float sm = p;
    #pragma unroll
    for (int o = 16; o > 0; o >>= 1) sm += __shfl_xor_sync(0xffffffffu, sm, o);
    if (lane == 0) ssum[wid] = sm;
    __syncthreads();
    float tot = 0.f;
    #pragma unroll
    for (int w = 0; w < 16; w++) tot += ssum[w];
    s_sc[tid] = p / tot;
    __syncthreads();
    if (tid < EE) {
        float acc = 0.f;
        for (int l = 0; l < LL; l++) acc += s_sc[l] * kxb[(size_t)l * EE + tid];
        s_v[tid] = acc;
    }
    __syncthreads();
    if (tid < EE) {
        float acc = proj_b[tid];
        const float* w = proj_w + (size_t)tid * EE;
        for (int e = 0; e < EE; e++) acc += s_v[e] * w[e];
        s_v2[tid] = acc + g_vs[b * EE + tid];
    }
    __syncthreads();
    if (tid < EE) {
        float acc = mlp_b[tid];
        const float* w = mlp_w + (size_t)tid * EE;
        for (int e = 0; e < EE; e++) acc += s_v2[e] * w[e];
        s_v[tid] = tanhf(acc);
    }
    __syncthreads();
    if (wid < 3) {
        const float* w = dense_w + (size_t)wid * EE;
        float acc = 0.f;
        for (int e = lane; e < EE; e += 32) acc += s_v[e] * w[e];
        #pragma unroll
        for (int o = 16; o > 0; o >>= 1) acc += __shfl_xor_sync(0xffffffffu, acc, o);
        if (lane == 0) out[b * 3 + wid] = acc + dense_b[wid];
    }
}

extern "C" void kernel_launch(void* const* d_in, const int* in_sizes, int n_in,
                              void* d_out, int out_size)
{
    const int*   text  = (const int*)d_in[0];
    const int*   aspi  = (const int*)d_in[1];
    const int*   xl    = (const int*)d_in[2];
    const int*   xr    = (const int*)d_in[3];
    const float* emb   = (const float*)d_in[4];
    const float* emb_a = (const float*)d_in[5];
    const float* Wih_l = (const float*)d_in[6];
    const float* Whh_l = (const float*)d_in[7];
    const float* bih_l = (const float*)d_in[8];
    const float* bhh_l = (const float*)d_in[9];
    const float* Wih_r = (const float*)d_in[10];
    const float* Whh_r = (const float*)d_in[11];
    const float* bih_r = (const float*)d_in[12];
    const float* bhh_r = (const float*)d_in[13];
    const float* mlw_l = (const float*)d_in[14];
    const float* mlb_l = (const float*)d_in[15];
    const float* mlw_r = (const float*)d_in[16];
    const float* mlb_r = (const float*)d_in[17];
    const float* w_k   = (const float*)d_in[18];
    const float* b_k   = (const float*)d_in[19];
    const float* w_q   = (const float*)d_in[20];
    const float* b_q   = (const float*)d_in[21];
    const float* aw    = (const float*)d_in[22];
    const float* pw    = (const float*)d_in[23];
    const float* pb    = (const float*)d_in[24];
    const float* mw    = (const float*)d_in[25];
    const float* mb    = (const float*)d_in[26];
    const float* dw    = (const float*)d_in[27];
    const float* db    = (const float*)d_in[28];
    float* out = (float*)d_out;

    k_wt<<<dim3(G3, 2), HH>>>(Whh_l, Whh_r);
    k_init<<<BB, 512>>>(text, aspi, xl, xr, emb_a, w_q, b_q, aw, mlb_l, mlb_r);
    k_sort<<<1, 256>>>();

    dim3 gx((G3 + 63) / 64, LL / 64, BB);
    k_gemm<<<gx, 256>>>(emb, xl, Wih_l, bih_l, G3, 0, 1);
    k_gemm<<<gx, 256>>>(emb, xr, Wih_r, bih_r, G3, 1, 2);

    k_gru2<<<BB, 320>>>(bhh_l, bhh_r, mlw_l, mlb_l, mlw_r, mlb_r);

    k_mem<<<dim3(LL, BB), 320>>>(text, emb);
    k_vs<<<BB, 320>>>();

    dim3 gk((EE + 63) / 64, LL / 64, BB);
    k_gemm<<<gk, 256>>>(emb, (const int*)0, w_k, b_k, EE, 2, 0);

    k_tail<<<BB, 512>>>(aw, pw, pb, mw, mb, dw, db, out);
}

// round 5
// speedup vs baseline: 3.5857x; 3.5857x over previous
#include <cuda_runtime.h>
#include <cuda_bf16.h>
#include <math.h>

#define BB 128
#define LL 512
#define LAa 8
#define EE 300
#define HH 300
#define G3 900

__device__ __align__(16) int   g_mem_len[BB];
__device__ __align__(16) int   g_asp_len[BB];
__device__ __align__(16) int   g_left_len[BB];
__device__ __align__(16) int   g_right_len[BB];
__device__ __align__(16) int   g_order_l[BB];
__device__ __align__(16) int   g_order_r[BB];
__device__ __align__(16) float g_qdot[BB];
__device__ __align__(16) float g_attn_l[BB * LL];
__device__ __align__(16) float g_attn_r[BB * LL];
__device__ __align__(16) float g_Wt_l[HH * G3];   // Wt[k*900+g] = Whh[g*300+k]
__device__ __align__(16) float g_Wt_r[HH * G3];
__device__ __align__(16) float g_xp_l[(size_t)BB * LL * G3];
__device__ __align__(16) float g_xp_r[(size_t)BB * LL * G3];
__device__ __align__(16) float g_memory[(size_t)BB * LL * EE];
__device__ __align__(16) float g_kx[(size_t)BB * LL * EE];
__device__ __align__(16) float g_vs[BB * EE];

__device__ __forceinline__ float sigf(float x) { return 1.0f / (1.0f + expf(-x)); }

// ---------------- K_wt: transpose both W_hh into gate-major layout ------------
__global__ void k_wt(const float* __restrict__ Whh_l, const float* __restrict__ Whh_r)
{
    int g = blockIdx.x, side = blockIdx.y, k = threadIdx.x;  // k in [0,300)
    const float* W = side ? Whh_r : Whh_l;
    float* Wt = side ? g_Wt_r : g_Wt_l;
    Wt[(size_t)k * G3 + g] = W[(size_t)g * HH + k];
}

// ---------------- K0: lengths, attn defaults, aspect mean -> qdot -------------
__global__ void k_init(const int* __restrict__ text, const int* __restrict__ aspi,
                       const int* __restrict__ xl, const int* __restrict__ xr,
                       const float* __restrict__ emb_aspect,
                       const float* __restrict__ w_q, const float* __restrict__ b_q,
                       const float* __restrict__ attn_w,
                       const float* __restrict__ mlp_l_b, const float* __restrict__ mlp_r_b)
{
    int b = blockIdx.x, tid = threadIdx.x;
    int ml = __syncthreads_count(text[b * LL + tid] != 0);
    int ll = __syncthreads_count(xl[b * LL + tid] != 0);
    int rl = __syncthreads_count(xr[b * LL + tid] != 0);
    int al = __syncthreads_count((tid < LAa) && (aspi[b * LAa + tid] != 0));
    if (tid == 0) { g_mem_len[b] = ml; g_left_len[b] = ll; g_right_len[b] = rl; g_asp_len[b] = al; }
    g_attn_l[b * LL + tid] = sigf(mlp_l_b[0]) + 0.5f;
    g_attn_r[b * LL + tid] = sigf(mlp_r_b[0]) + 0.5f;

    __shared__ float s_asp[EE];
    __shared__ float sred[16];
    if (tid < EE) {
        float acc = 0.f;
        #pragma unroll
        for (int a = 0; a < LAa; a++)
            if (a < al) acc += emb_aspect[(size_t)aspi[b * LAa + a] * EE + tid];
        s_asp[tid] = acc / (float)al;
    }
    __syncthreads();
    float val = 0.f;
    if (tid < EE) {
        float acc = b_q[tid];
        const float* wq = w_q + (size_t)tid * EE;
        for (int e = 0; e < EE; e++) acc += s_asp[e] * wq[e];
        val = acc * attn_w[EE + tid];
    }
    #pragma unroll
    for (int o = 16; o > 0; o >>= 1) val += __shfl_xor_sync(0xffffffffu, val, o);
    if ((tid & 31) == 0) sred[tid >> 5] = val;
    __syncthreads();
    if (tid == 0) {
        float s = 0.f;
        #pragma unroll
        for (int w = 0; w < 16; w++) s += sred[w];
        g_qdot[b] = s;
    }
}

// ---------------- K_sort: rank-sort sequence lengths (desc) per side ----------
__global__ void k_sort()
{
    int tid = threadIdx.x;            // 256 threads
    int side = tid >> 7, i = tid & 127;
    const int* lens = side ? g_right_len : g_left_len;
    int* ord = side ? g_order_r : g_order_l;
    int li = lens[i], r = 0;
    for (int j = 0; j < BB; j++) {
        int lj = lens[j];
        r += (lj > li) || (lj == li && j < i);
    }
    ord[r] = i;
}

// ---------------- K1: tiled fp32 GEMM ----------------------------------------
__global__ void __launch_bounds__(256) k_gemm(
    const float* __restrict__ Aext, const int* __restrict__ ids,
    const float* __restrict__ W, const float* __restrict__ bias,
    int N, int dst_sel, int limit_sel)
{
    const int K = EE;
    int b = blockIdx.z, m0 = blockIdx.y * 64, n0 = blockIdx.x * 64;
    int lim = (limit_sel == 1) ? g_left_len[b] : (limit_sel == 2) ? g_right_len[b] : LL;
    if (m0 >= lim) return;

    float* C = (dst_sel == 0) ? g_xp_l : (dst_sel == 1) ? g_xp_r : g_kx;
    float* Cb = C + (size_t)b * LL * N;
    const int* bids = ids ? (ids + (size_t)b * LL) : (const int*)0;

    __shared__ float As[16][64];
    __shared__ float Bs[16][64];

    int tid = threadIdx.x;
    int tx = tid & 15, ty = tid >> 4;
    int lrow = tid >> 2, lc4 = (tid & 3) << 2;

    int gm = m0 + lrow;
    const float* arow;
    if (bids) arow = Aext + (size_t)bids[gm] * K;
    else      arow = g_memory + ((size_t)b * LL + gm) * K;
    int gn = n0 + lrow;
    const float* brow = (gn < N) ? (W + (size_t)gn * K) : (const float*)0;

    float acc[4][4];
    #pragma unroll
    for (int i = 0; i < 4; i++)
        #pragma unroll
        for (int j = 0; j < 4; j++) acc[i][j] = 0.f;

    for (int k0 = 0; k0 < K; k0 += 16) {
        float4 av = make_float4(0.f, 0.f, 0.f, 0.f);
        float4 bv = make_float4(0.f, 0.f, 0.f, 0.f);
        if (k0 + lc4 < K) {
            av = *(const float4*)(arow + k0 + lc4);
            if (brow) bv = *(const float4*)(brow + k0 + lc4);
        }
        __syncthreads();
        As[lc4 + 0][lrow] = av.x; As[lc4 + 1][lrow] = av.y;
        As[lc4 + 2][lrow] = av.z; As[lc4 + 3][lrow] = av.w;
        Bs[lc4 + 0][lrow] = bv.x; Bs[lc4 + 1][lrow] = bv.y;
        Bs[lc4 + 2][lrow] = bv.z; Bs[lc4 + 3][lrow] = bv.w;
        __syncthreads();
        #pragma unroll
        for (int kk = 0; kk < 16; kk++) {
            float4 a  = *(const float4*)&As[kk][ty << 2];
            float4 bb = *(const float4*)&Bs[kk][tx << 2];
            acc[0][0] += a.x * bb.x; acc[0][1] += a.x * bb.y; acc[0][2] += a.x * bb.z; acc[0][3] += a.x * bb.w;
            acc[1][0] += a.y * bb.x; acc[1][1] += a.y * bb.y; acc[1][2] += a.y * bb.z; acc[1][3] += a.y * bb.w;
            acc[2][0] += a.z * bb.x; acc[2][1] += a.z * bb.y; acc[2][2] += a.z * bb.z; acc[2][3] += a.z * bb.w;
            acc[3][0] += a.w * bb.x; acc[3][1] += a.w * bb.y; acc[3][2] += a.w * bb.z; acc[3][3] += a.w * bb.w;
        }
    }
    #pragma unroll
    for (int i = 0; i < 4; i++) {
        int om = m0 + (ty << 2) + i;
        #pragma unroll
        for (int j = 0; j < 4; j++) {
            int on = n0 + (tx << 2) + j;
            if (on < N) Cb[(size_t)om * N + on] = acc[i][j] + bias[on];
        }
    }
}

// ---------------- K2: GRU v3 — 480 thr, 2-way k-split, anti-sorted pairs ------
// Blocks 0..63: left, 64..127: right. Block pb pairs seq ord[pb] (A, long)
// with ord[127-pb] (B, short).
// Phase A: threads 0..449: group=(tid>=225), idx=tid%225; each computes 4 gate
//          partials over 150 k-values (coalesced float4, pointer increments).
// Phase B: threads 0..299 sum partials, gate math, attn reduction.
__global__ void __launch_bounds__(480, 1) k_gru3(
    const float* __restrict__ bhh_l, const float* __restrict__ bhh_r,
    const float* __restrict__ mlpw_l, const float* __restrict__ mlpb_l,
    const float* __restrict__ mlpw_r, const float* __restrict__ mlpb_r)
{
    int side = (blockIdx.x >= 64);
    int pb = blockIdx.x & 63;
    const float* Wt   = side ? g_Wt_r : g_Wt_l;
    const float* bhh  = side ? bhh_r : bhh_l;
    const float* mlpw = side ? mlpw_r : mlpw_l;
    float mbb         = side ? mlpb_r[0] : mlpb_l[0];
    const float* xp   = side ? g_xp_r : g_xp_l;
    const int* lens   = side ? g_right_len : g_left_len;
    const int* ord    = side ? g_order_r : g_order_l;
    float* attn       = side ? g_attn_r : g_attn_l;

    int sA = ord[pb], sB = ord[127 - pb];
    int lenA = lens[sA], lenB = lens[sB];   // lenA >= lenB

    int tid = threadIdx.x, lane = tid & 31, wid = tid >> 5;

    __shared__ float2 s_h[EE];
    __shared__ float  s_part[2][2][G3];     // [kgroup][seq][gate]
    __shared__ float  parts[2][10];

    bool pa = (tid < 450);
    int grp = (tid >= 225) ? 1 : 0;
    int idx = tid - grp * 225;
    const float4* Wbase = ((const float4*)Wt) + grp * (150 * 225) + idx;

    float wm = 0.f, bhr = 0.f, bhz = 0.f, bhn = 0.f;
    if (tid < EE) {
        wm = mlpw[tid];
        bhr = bhh[tid]; bhz = bhh[HH + tid]; bhn = bhh[2 * HH + tid];
        s_h[tid] = make_float2(0.f, 0.f);
    }
    const float* xpA = xp + (size_t)sA * LL * G3;
    const float* xpB = xp + (size_t)sB * LL * G3;
    __syncthreads();

    for (int t = 0; t < lenA; t++) {
        bool aB = (t < lenB);
        // xp prefetch (threads < 300)
        float gA0 = 0.f, gA1 = 0.f, gA2 = 0.f, gB0 = 0.f, gB1 = 0.f, gB2 = 0.f;
        if (tid < EE) {
            const float* g = xpA + (size_t)t * G3;
            gA0 = g[tid]; gA1 = g[HH + tid]; gA2 = g[2 * HH + tid];
            if (aB) {
                const float* h = xpB + (size_t)t * G3;
                gB0 = h[tid]; gB1 = h[HH + tid]; gB2 = h[2 * HH + tid];
            }
        }
        // Phase A
        if (pa) {
            const float4* wp = Wbase;
            const float2* hp = s_h + grp * 150;
            float a0 = 0.f, a1 = 0.f, a2 = 0.f, a3 = 0.f;
            if (aB) {
                float b0 = 0.f, b1 = 0.f, b2 = 0.f, b3 = 0.f;
                #pragma unroll 5
                for (int k = 0; k < 150; k++) {
                    float4 w = *wp; wp += 225;
                    float2 h = hp[k];
                    a0 = fmaf(w.x, h.x, a0); a1 = fmaf(w.y, h.x, a1);
                    a2 = fmaf(w.z, h.x, a2); a3 = fmaf(w.w, h.x, a3);
                    b0 = fmaf(w.x, h.y, b0); b1 = fmaf(w.y, h.y, b1);
                    b2 = fmaf(w.z, h.y, b2); b3 = fmaf(w.w, h.y, b3);
                }
                *(float4*)&s_part[grp][1][idx * 4] = make_float4(b0, b1, b2, b3);
            } else {
                #pragma unroll 5
                for (int k = 0; k < 150; k++) {
                    float4 w = *wp; wp += 225;
                    float hx = hp[k].x;
                    a0 = fmaf(w.x, hx, a0); a1 = fmaf(w.y, hx, a1);
                    a2 = fmaf(w.z, hx, a2); a3 = fmaf(w.w, hx, a3);
                }
            }
            *(float4*)&s_part[grp][0][idx * 4] = make_float4(a0, a1, a2, a3);
        }
        __syncthreads();
        // Phase B
        float vA = 0.f, vB = 0.f;
        if (tid < EE) {
            float2 h = s_h[tid];
            {
                float rp = s_part[0][0][tid] + s_part[1][0][tid];
                float zp = s_part[0][0][HH + tid] + s_part[1][0][HH + tid];
                float np = s_part[0][0][2 * HH + tid] + s_part[1][0][2 * HH + tid];
                float r = sigf(gA0 + rp + bhr);
                float z = sigf(gA1 + zp + bhz);
                float n = tanhf(gA2 + r * (np + bhn));
                h.x = (1.f - z) * n + z * h.x;
                vA = h.x * wm;
            }
            if (aB) {
                float rp = s_part[0][1][tid] + s_part[1][1][tid];
                float zp = s_part[0][1][HH + tid] + s_part[1][1][HH + tid];
                float np = s_part[0][1][2 * HH + tid] + s_part[1][1][2 * HH + tid];
                float r = sigf(gB0 + rp + bhr);
                float z = sigf(gB1 + zp + bhz);
                float n = tanhf(gB2 + r * (np + bhn));
                h.y = (1.f - z) * n + z * h.y;
                vB = h.y * wm;
            }
            s_h[tid] = h;
        }
        #pragma unroll
        for (int o = 16; o > 0; o >>= 1) {
            vA += __shfl_xor_sync(0xffffffffu, vA, o);
            vB += __shfl_xor_sync(0xffffffffu, vB, o);
        }
        if (lane == 0 && wid < 10) { parts[0][wid] = vA; parts[1][wid] = vB; }
        __syncthreads();
        if (tid == 0) {
            float s = 0.f;
            #pragma unroll
            for (int w = 0; w < 10; w++) s += parts[0][w];
            attn[sA * LL + t] = sigf(s + mbb) + 0.5f;
        }
        if (tid == 32 && aB) {
            float s = 0.f;
            #pragma unroll
            for (int w = 0; w < 10; w++) s += parts[1][w];
            attn[sB * LL + t] = sigf(s + mbb) + 0.5f;
        }
    }
}

// ---------------- K3: memory = emb[text] * scale ------------------------------
__global__ void k_mem(const int* __restrict__ text, const float* __restrict__ emb)
{
    int l = blockIdx.x, b = blockIdx.y, tid = threadIdx.x;
    if (tid >= EE) return;
    float* row = g_memory + ((size_t)b * LL + l) * EE;
    int ml = g_mem_len[b];
    if (l >= ml) { row[tid] = 0.f; return; }
    int astart = g_left_len[b] - g_asp_len[b];
    int aend = g_left_len[b];
    float al = g_attn_l[b * LL + l];
    int ridx = min(max(l - astart, 0), LL - 1);
    float arv = g_attn_r[b * LL + ridx];
    float sc = (l < astart) ? al : ((l < aend) ? (al + arv) : arv);
    int id = text[b * LL + l];
    row[tid] = emb[(size_t)id * EE + tid] * sc;
}

// ---------------- K4: v_s -----------------------------------------------------
__global__ void k_vs()
{
    int b = blockIdx.x, tid = threadIdx.x;
    if (tid >= EE) return;
    float acc = 0.f;
    const float* p = g_memory + (size_t)b * LL * EE + tid;
    for (int l = 0; l < LL; l++) acc += p[(size_t)l * EE];
    g_vs[b * EE + tid] = acc / (float)g_mem_len[b];
}

// ---------------- K5: score->softmax->v_ts->proj->mlp->dense ------------------
__global__ void __launch_bounds__(512) k_tail(
    const float* __restrict__ attn_w,
    const float* __restrict__ proj_w, const float* __restrict__ proj_b,
    const float* __restrict__ mlp_w, const float* __restrict__ mlp_b,
    const float* __restrict__ dense_w, const float* __restrict__ dense_b,
    float* __restrict__ out)
{
    int b = blockIdx.x, tid = threadIdx.x, lane = tid & 31, wid = tid >> 5;
    __shared__ float s_aw[EE];
    __shared__ float s_sc[LL];
    __shared__ float smax[16], ssum[16];
    __shared__ float s_v[EE], s_v2[EE];
    const float* kxb = g_kx + (size_t)b * LL * EE;
    if (tid < EE) s_aw[tid] = attn_w[tid];
    __syncthreads();
    float qd = g_qdot[b];
    for (int l = wid; l < LL; l += 16) {
        const float* row = kxb + (size_t)l * EE;
        float acc = 0.f;
        for (int e = lane; e < EE; e += 32) acc += row[e] * s_aw[e];
        #pragma unroll
        for (int o = 16; o > 0; o >>= 1) acc += __shfl_xor_sync(0xffffffffu, acc, o);
        if (lane == 0) s_sc[l] = tanhf(acc + qd);
    }
    __syncthreads();
    float x = s_sc[tid];
    float m = x;
    #pragma unroll
    for (int o = 16; o > 0; o >>= 1) m = fmaxf(m, __shfl_xor_sync(0xffffffffu, m, o));
    if (lane == 0) smax[wid] = m;
    __syncthreads();
    float bm = smax[0];
    #pragma unroll
    for (int w = 1; w < 16; w++) bm = fmaxf(bm, smax[w]);
    float p = expf(x - bm);
    float sm = p;
    #pragma unroll
    for (int o = 16; o > 0; o >>= 1) sm += __shfl_xor_sync(0xffffffffu, sm, o);
    if (lane == 0) ssum[wid] = sm;
    __syncthreads();
    float tot = 0.f;
    #pragma unroll
    for (int w = 0; w < 16; w++) tot += ssum[w];
    s_sc[tid] = p / tot;
    __syncthreads();
    if (tid < EE) {
        float acc = 0.f;
        for (int l = 0; l < LL; l++) acc += s_sc[l] * kxb[(size_t)l * EE + tid];
        s_v[tid] = acc;
    }
    __syncthreads();
    if (tid < EE) {
        float acc = proj_b[tid];
        const float* w = proj_w + (size_t)tid * EE;
        for (int e = 0; e < EE; e++) acc += s_v[e] * w[e];
        s_v2[tid] = acc + g_vs[b * EE + tid];
    }
    __syncthreads();
    if (tid < EE) {
        float acc = mlp_b[tid];
        const float* w = mlp_w + (size_t)tid * EE;
        for (int e = 0; e < EE; e++) acc += s_v2[e] * w[e];
        s_v[tid] = tanhf(acc);
    }
    __syncthreads();
    if (wid < 3) {
        const float* w = dense_w + (size_t)wid * EE;
        float acc = 0.f;
        for (int e = lane; e < EE; e += 32) acc += s_v[e] * w[e];
        #pragma unroll
        for (int o = 16; o > 0; o >>= 1) acc += __shfl_xor_sync(0xffffffffu, acc, o);
        if (lane == 0) out[b * 3 + wid] = acc + dense_b[wid];
    }
}

extern "C" void kernel_launch(void* const* d_in, const int* in_sizes, int n_in,
                              void* d_out, int out_size)
{
    const int*   text  = (const int*)d_in[0];
    const int*   aspi  = (const int*)d_in[1];
    const int*   xl    = (const int*)d_in[2];
    const int*   xr    = (const int*)d_in[3];
    const float* emb   = (const float*)d_in[4];
    const float* emb_a = (const float*)d_in[5];
    const float* Wih_l = (const float*)d_in[6];
    const float* Whh_l = (const float*)d_in[7];
    const float* bih_l = (const float*)d_in[8];
    const float* bhh_l = (const float*)d_in[9];
    const float* Wih_r = (const float*)d_in[10];
    const float* Whh_r = (const float*)d_in[11];
    const float* bih_r = (const float*)d_in[12];
    const float* bhh_r = (const float*)d_in[13];
    const float* mlw_l = (const float*)d_in[14];
    const float* mlb_l = (const float*)d_in[15];
    const float* mlw_r = (const float*)d_in[16];
    const float* mlb_r = (const float*)d_in[17];
    const float* w_k   = (const float*)d_in[18];
    const float* b_k   = (const float*)d_in[19];
    const float* w_q   = (const float*)d_in[20];
    const float* b_q   = (const float*)d_in[21];
    const float* aw    = (const float*)d_in[22];
    const float* pw    = (const float*)d_in[23];
    const float* pb    = (const float*)d_in[24];
    const float* mw    = (const float*)d_in[25];
    const float* mb    = (const float*)d_in[26];
    const float* dw    = (const float*)d_in[27];
    const float* db    = (const float*)d_in[28];
    float* out = (float*)d_out;

    k_wt<<<dim3(G3, 2), HH>>>(Whh_l, Whh_r);
    k_init<<<BB, 512>>>(text, aspi, xl, xr, emb_a, w_q, b_q, aw, mlb_l, mlb_r);
    k_sort<<<1, 256>>>();

    dim3 gx((G3 + 63) / 64, LL / 64, BB);
    k_gemm<<<gx, 256>>>(emb, xl, Wih_l, bih_l, G3, 0, 1);
    k_gemm<<<gx, 256>>>(emb, xr, Wih_r, bih_r, G3, 1, 2);

    k_gru3<<<BB, 480>>>(bhh_l, bhh_r, mlw_l, mlb_l, mlw_r, mlb_r);

    k_mem<<<dim3(LL, BB), 320>>>(text, emb);
    k_vs<<<BB, 320>>>();

    dim3 gk((EE + 63) / 64, LL / 64, BB);
    k_gemm<<<gk, 256>>>(emb, (const int*)0, w_k, b_k, EE, 2, 0);

    k_tail<<<BB, 512>>>(aw, pw, pb, mw, mb, dw, db, out);
}

// round 6
// speedup vs baseline: 4.3909x; 1.2245x over previous
#include <cuda_runtime.h>
#include <cuda_bf16.h>
#include <math.h>

#define BB 128
#define LL 512
#define LAa 8
#define EE 300
#define HH 300
#define G3 900

__device__ __align__(16) int   g_mem_len[BB];
__device__ __align__(16) int   g_asp_len[BB];
__device__ __align__(16) int   g_left_len[BB];
__device__ __align__(16) int   g_right_len[BB];
__device__ __align__(16) int   g_order_l[BB];
__device__ __align__(16) int   g_order_r[BB];
__device__ __align__(16) float g_qdot[BB];
__device__ __align__(16) float g_attn_l[BB * LL];
__device__ __align__(16) float g_attn_r[BB * LL];
// Wtb[k2*900+g] = bf162( Whh[g][2k2], Whh[g][2k2+1] )
__device__ __align__(16) __nv_bfloat162 g_Wtb_l[150 * G3];
__device__ __align__(16) __nv_bfloat162 g_Wtb_r[150 * G3];
__device__ __align__(16) float g_xp_l[(size_t)BB * LL * G3];
__device__ __align__(16) float g_xp_r[(size_t)BB * LL * G3];
__device__ __align__(16) float g_memory[(size_t)BB * LL * EE];
__device__ __align__(16) float g_kx[(size_t)BB * LL * EE];
__device__ __align__(16) float g_vs[BB * EE];

__device__ __forceinline__ float sigf(float x) { return 1.0f / (1.0f + expf(-x)); }

// ---------------- K_wtb: pack W_hh into k-paired bf16 gate-major layout -------
__global__ void k_wtb(const float* __restrict__ Whh_l, const float* __restrict__ Whh_r)
{
    int g = blockIdx.x, side = blockIdx.y, k2 = threadIdx.x;   // k2 in [0,150)
    const float* W = side ? Whh_r : Whh_l;
    __nv_bfloat162* Wt = side ? g_Wtb_r : g_Wtb_l;
    float v0 = W[(size_t)g * HH + 2 * k2];
    float v1 = W[(size_t)g * HH + 2 * k2 + 1];
    Wt[(size_t)k2 * G3 + g] = __floats2bfloat162_rn(v0, v1);
}

// ---------------- K0: lengths, attn defaults, aspect mean -> qdot -------------
__global__ void k_init(const int* __restrict__ text, const int* __restrict__ aspi,
                       const int* __restrict__ xl, const int* __restrict__ xr,
                       const float* __restrict__ emb_aspect,
                       const float* __restrict__ w_q, const float* __restrict__ b_q,
                       const float* __restrict__ attn_w,
                       const float* __restrict__ mlp_l_b, const float* __restrict__ mlp_r_b)
{
    int b = blockIdx.x, tid = threadIdx.x;
    int ml = __syncthreads_count(text[b * LL + tid] != 0);
    int ll = __syncthreads_count(xl[b * LL + tid] != 0);
    int rl = __syncthreads_count(xr[b * LL + tid] != 0);
    int al = __syncthreads_count((tid < LAa) && (aspi[b * LAa + tid] != 0));
    if (tid == 0) { g_mem_len[b] = ml; g_left_len[b] = ll; g_right_len[b] = rl; g_asp_len[b] = al; }
    g_attn_l[b * LL + tid] = sigf(mlp_l_b[0]) + 0.5f;
    g_attn_r[b * LL + tid] = sigf(mlp_r_b[0]) + 0.5f;

    __shared__ float s_asp[EE];
    __shared__ float sred[16];
    if (tid < EE) {
        float acc = 0.f;
        #pragma unroll
        for (int a = 0; a < LAa; a++)
            if (a < al) acc += emb_aspect[(size_t)aspi[b * LAa + a] * EE + tid];
        s_asp[tid] = acc / (float)al;
    }
    __syncthreads();
    float val = 0.f;
    if (tid < EE) {
        float acc = b_q[tid];
        const float* wq = w_q + (size_t)tid * EE;
        for (int e = 0; e < EE; e++) acc += s_asp[e] * wq[e];
        val = acc * attn_w[EE + tid];
    }
    #pragma unroll
    for (int o = 16; o > 0; o >>= 1) val += __shfl_xor_sync(0xffffffffu, val, o);
    if ((tid & 31) == 0) sred[tid >> 5] = val;
    __syncthreads();
    if (tid == 0) {
        float s = 0.f;
        #pragma unroll
        for (int w = 0; w < 16; w++) s += sred[w];
        g_qdot[b] = s;
    }
}

// ---------------- K_sort: rank-sort sequence lengths (desc) per side ----------
__global__ void k_sort()
{
    int tid = threadIdx.x;            // 256 threads
    int side = tid >> 7, i = tid & 127;
    const int* lens = side ? g_right_len : g_left_len;
    int* ord = side ? g_order_r : g_order_l;
    int li = lens[i], r = 0;
    for (int j = 0; j < BB; j++) {
        int lj = lens[j];
        r += (lj > li) || (lj == li && j < i);
    }
    ord[r] = i;
}

// ---------------- K1: tiled fp32 GEMM ----------------------------------------
__global__ void __launch_bounds__(256) k_gemm(
    const float* __restrict__ Aext, const int* __restrict__ ids,
    const float* __restrict__ W, const float* __restrict__ bias,
    int N, int dst_sel, int limit_sel)
{
    const int K = EE;
    int b = blockIdx.z, m0 = blockIdx.y * 64, n0 = blockIdx.x * 64;
    int lim = (limit_sel == 1) ? g_left_len[b] : (limit_sel == 2) ? g_right_len[b] : LL;
    if (m0 >= lim) return;

    float* C = (dst_sel == 0) ? g_xp_l : (dst_sel == 1) ? g_xp_r : g_kx;
    float* Cb = C + (size_t)b * LL * N;
    const int* bids = ids ? (ids + (size_t)b * LL) : (const int*)0;

    __shared__ float As[16][64];
    __shared__ float Bs[16][64];

    int tid = threadIdx.x;
    int tx = tid & 15, ty = tid >> 4;
    int lrow = tid >> 2, lc4 = (tid & 3) << 2;

    int gm = m0 + lrow;
    const float* arow;
    if (bids) arow = Aext + (size_t)bids[gm] * K;
    else      arow = g_memory + ((size_t)b * LL + gm) * K;
    int gn = n0 + lrow;
    const float* brow = (gn < N) ? (W + (size_t)gn * K) : (const float*)0;

    float acc[4][4];
    #pragma unroll
    for (int i = 0; i < 4; i++)
        #pragma unroll
        for (int j = 0; j < 4; j++) acc[i][j] = 0.f;

    for (int k0 = 0; k0 < K; k0 += 16) {
        float4 av = make_float4(0.f, 0.f, 0.f, 0.f);
        float4 bv = make_float4(0.f, 0.f, 0.f, 0.f);
        if (k0 + lc4 < K) {
            av = *(const float4*)(arow + k0 + lc4);
            if (brow) bv = *(const float4*)(brow + k0 + lc4);
        }
        __syncthreads();
        As[lc4 + 0][lrow] = av.x; As[lc4 + 1][lrow] = av.y;
        As[lc4 + 2][lrow] = av.z; As[lc4 + 3][lrow] = av.w;
        Bs[lc4 + 0][lrow] = bv.x; Bs[lc4 + 1][lrow] = bv.y;
        Bs[lc4 + 2][lrow] = bv.z; Bs[lc4 + 3][lrow] = bv.w;
        __syncthreads();
        #pragma unroll
        for (int kk = 0; kk < 16; kk++) {
            float4 a  = *(const float4*)&As[kk][ty << 2];
            float4 bb = *(const float4*)&Bs[kk][tx << 2];
            acc[0][0] += a.x * bb.x; acc[0][1] += a.x * bb.y; acc[0][2] += a.x * bb.z; acc[0][3] += a.x * bb.w;
            acc[1][0] += a.y * bb.x; acc[1][1] += a.y * bb.y; acc[1][2] += a.y * bb.z; acc[1][3] += a.y * bb.w;
            acc[2][0] += a.z * bb.x; acc[2][1] += a.z * bb.y; acc[2][2] += a.z * bb.z; acc[2][3] += a.z * bb.w;
            acc[3][0] += a.w * bb.x; acc[3][1] += a.w * bb.y; acc[3][2] += a.w * bb.z; acc[3][3] += a.w * bb.w;
        }
    }
    #pragma unroll
    for (int i = 0; i < 4; i++) {
        int om = m0 + (ty << 2) + i;
        #pragma unroll
        for (int j = 0; j < 4; j++) {
            int on = n0 + (tx << 2) + j;
            if (on < N) Cb[(size_t)om * N + on] = acc[i][j] + bias[on];
        }
    }
}

// ---------------- K2: GRU v4 — bf16 weights, 2-way k-split, anti-sorted pairs -
// 480 threads. Phase A threads 0..449: grp=(tid>=225), idx=tid-225*grp.
// Each owns gates 4idx..4idx+3 over k2 in [grp*75, grp*75+75) (k pairs).
// One LDG.128 per iter = 4 gates x 2 k's in bf16; unpack via bit shifts; fp32 FMA.
__global__ void __launch_bounds__(480, 1) k_gru4(
    const float* __restrict__ bhh_l, const float* __restrict__ bhh_r,
    const float* __restrict__ mlpw_l, const float* __restrict__ mlpb_l,
    const float* __restrict__ mlpw_r, const float* __restrict__ mlpb_r)
{
    int side = (blockIdx.x >= 64);
    int pb = blockIdx.x & 63;
    const __nv_bfloat162* Wt = side ? g_Wtb_r : g_Wtb_l;
    const float* bhh  = side ? bhh_r : bhh_l;
    const float* mlpw = side ? mlpw_r : mlpw_l;
    float mbb         = side ? mlpb_r[0] : mlpb_l[0];
    const float* xp   = side ? g_xp_r : g_xp_l;
    const int* lens   = side ? g_right_len : g_left_len;
    const int* ord    = side ? g_order_r : g_order_l;
    float* attn       = side ? g_attn_r : g_attn_l;

    int sA = ord[pb], sB = ord[127 - pb];
    int lenA = lens[sA], lenB = lens[sB];   // lenA >= lenB

    int tid = threadIdx.x, lane = tid & 31, wid = tid >> 5;

    __shared__ __align__(16) float2 s_h[EE];
    __shared__ float  s_part[2][2][G3];     // [kgroup][seq][gate]
    __shared__ float  parts[2][10];

    bool pa = (tid < 450);
    int grp = (tid >= 225) ? 1 : 0;
    int idx = tid - grp * 225;
    // uint4 = 4 consecutive bf162 = gates 4idx..4idx+3 at one k2. row stride = 225 uint4.
    const uint4* Wbase = ((const uint4*)Wt) + grp * (75 * 225) + idx;

    float wm = 0.f, bhr = 0.f, bhz = 0.f, bhn = 0.f;
    if (tid < EE) {
        wm = mlpw[tid];
        bhr = bhh[tid]; bhz = bhh[HH + tid]; bhn = bhh[2 * HH + tid];
        s_h[tid] = make_float2(0.f, 0.f);
    }
    const float* xpA = xp + (size_t)sA * LL * G3;
    const float* xpB = xp + (size_t)sB * LL * G3;
    __syncthreads();

    for (int t = 0; t < lenA; t++) {
        bool aB = (t < lenB);
        float gA0 = 0.f, gA1 = 0.f, gA2 = 0.f, gB0 = 0.f, gB1 = 0.f, gB2 = 0.f;
        if (tid < EE) {
            const float* g = xpA + (size_t)t * G3;
            gA0 = g[tid]; gA1 = g[HH + tid]; gA2 = g[2 * HH + tid];
            if (aB) {
                const float* h = xpB + (size_t)t * G3;
                gB0 = h[tid]; gB1 = h[HH + tid]; gB2 = h[2 * HH + tid];
            }
        }
        // Phase A
        if (pa) {
            const uint4* wp = Wbase;
            // float4 view of s_h: (hA[2k2], hB[2k2], hA[2k2+1], hB[2k2+1])
            const float4* hp = ((const float4*)s_h) + grp * 75;
            float a0 = 0.f, a1 = 0.f, a2 = 0.f, a3 = 0.f;
            float b0 = 0.f, b1 = 0.f, b2 = 0.f, b3 = 0.f;
            if (aB) {
                #pragma unroll 5
                for (int k = 0; k < 75; k++) {
                    uint4 w = *wp; wp += 225;
                    float4 h = hp[k];   // h.x=hA(2k) h.y=hB(2k) h.z=hA(2k+1) h.w=hB(2k+1)
                    float w0a = __int_as_float(w.x << 16), w0b = __int_as_float(w.x & 0xffff0000u);
                    float w1a = __int_as_float(w.y << 16), w1b = __int_as_float(w.y & 0xffff0000u);
                    float w2a = __int_as_float(w.z << 16), w2b = __int_as_float(w.z & 0xffff0000u);
                    float w3a = __int_as_float(w.w << 16), w3b = __int_as_float(w.w & 0xffff0000u);
                    a0 = fmaf(w0a, h.x, a0); a0 = fmaf(w0b, h.z, a0);
                    a1 = fmaf(w1a, h.x, a1); a1 = fmaf(w1b, h.z, a1);
                    a2 = fmaf(w2a, h.x, a2); a2 = fmaf(w2b, h.z, a2);
                    a3 = fmaf(w3a, h.x, a3); a3 = fmaf(w3b, h.z, a3);
                    b0 = fmaf(w0a, h.y, b0); b0 = fmaf(w0b, h.w, b0);
                    b1 = fmaf(w1a, h.y, b1); b1 = fmaf(w1b, h.w, b1);
                    b2 = fmaf(w2a, h.y, b2); b2 = fmaf(w2b, h.w, b2);
                    b3 = fmaf(w3a, h.y, b3); b3 = fmaf(w3b, h.w, b3);
                }
                *(float4*)&s_part[grp][1][idx * 4] = make_float4(b0, b1, b2, b3);
            } else {
                #pragma unroll 5
                for (int k = 0; k < 75; k++) {
                    uint4 w = *wp; wp += 225;
                    float4 h = hp[k];
                    float w0a = __int_as_float(w.x << 16), w0b = __int_as_float(w.x & 0xffff0000u);
                    float w1a = __int_as_float(w.y << 16), w1b = __int_as_float(w.y & 0xffff0000u);
                    float w2a = __int_as_float(w.z << 16), w2b = __int_as_float(w.z & 0xffff0000u);
                    float w3a = __int_as_float(w.w << 16), w3b = __int_as_float(w.w & 0xffff0000u);
                    a0 = fmaf(w0a, h.x, a0); a0 = fmaf(w0b, h.z, a0);
                    a1 = fmaf(w1a, h.x, a1); a1 = fmaf(w1b, h.z, a1);
                    a2 = fmaf(w2a, h.x, a2); a2 = fmaf(w2b, h.z, a2);
                    a3 = fmaf(w3a, h.x, a3); a3 = fmaf(w3b, h.z, a3);
                }
            }
            *(float4*)&s_part[grp][0][idx * 4] = make_float4(a0, a1, a2, a3);
        }
        __syncthreads();
        // Phase B
        float vA = 0.f, vB = 0.f;
        if (tid < EE) {
            float2 h = s_h[tid];
            {
                float rp = s_part[0][0][tid] + s_part[1][0][tid];
                float zp = s_part[0][0][HH + tid] + s_part[1][0][HH + tid];
                float np = s_part[0][0][2 * HH + tid] + s_part[1][0][2 * HH + tid];
                float r = sigf(gA0 + rp + bhr);
                float z = sigf(gA1 + zp + bhz);
                float n = tanhf(gA2 + r * (np + bhn));
                h.x = (1.f - z) * n + z * h.x;
                vA = h.x * wm;
            }
            if (aB) {
                float rp = s_part[0][1][tid] + s_part[1][1][tid];
                float zp = s_part[0][1][HH + tid] + s_part[1][1][HH + tid];
                float np = s_part[0][1][2 * HH + tid] + s_part[1][1][2 * HH + tid];
                float r = sigf(gB0 + rp + bhr);
                float z = sigf(gB1 + zp + bhz);
                float n = tanhf(gB2 + r * (np + bhn));
                h.y = (1.f - z) * n + z * h.y;
                vB = h.y * wm;
            }
            s_h[tid] = h;
        }
        #pragma unroll
        for (int o = 16; o > 0; o >>= 1) {
            vA += __shfl_xor_sync(0xffffffffu, vA, o);
            vB += __shfl_xor_sync(0xffffffffu, vB, o);
        }
        if (lane == 0 && wid < 10) { parts[0][wid] = vA; parts[1][wid] = vB; }
        __syncthreads();
        if (tid == 0) {
            float s = 0.f;
            #pragma unroll
            for (int w = 0; w < 10; w++) s += parts[0][w];
            attn[sA * LL + t] = sigf(s + mbb) + 0.5f;
        }
        if (tid == 32 && aB) {
            float s = 0.f;
            #pragma unroll
            for (int w = 0; w < 10; w++) s += parts[1][w];
            attn[sB * LL + t] = sigf(s + mbb) + 0.5f;
        }
    }
}

// ---------------- K3: memory = emb[text] * scale ------------------------------
__global__ void k_mem(const int* __restrict__ text, const float* __restrict__ emb)
{
    int l = blockIdx.x, b = blockIdx.y, tid = threadIdx.x;
    if (tid >= EE) return;
    float* row = g_memory + ((size_t)b * LL + l) * EE;
    int ml = g_mem_len[b];
    if (l >= ml) { row[tid] = 0.f; return; }
    int astart = g_left_len[b] - g_asp_len[b];
    int aend = g_left_len[b];
    float al = g_attn_l[b * LL + l];
    int ridx = min(max(l - astart, 0), LL - 1);
    float arv = g_attn_r[b * LL + ridx];
    float sc = (l < astart) ? al : ((l < aend) ? (al + arv) : arv);
    int id = text[b * LL + l];
    row[tid] = emb[(size_t)id * EE + tid] * sc;
}

// ---------------- K4: v_s -----------------------------------------------------
__global__ void k_vs()
{
    int b = blockIdx.x, tid = threadIdx.x;
    if (tid >= EE) return;
    float acc = 0.f;
    const float* p = g_memory + (size_t)b * LL * EE + tid;
    for (int l = 0; l < LL; l++) acc += p[(size_t)l * EE];
    g_vs[b * EE + tid] = acc / (float)g_mem_len[b];
}

// ---------------- K5: score->softmax->v_ts->proj->mlp->dense ------------------
__global__ void __launch_bounds__(512) k_tail(
    const float* __restrict__ attn_w,
    const float* __restrict__ proj_w, const float* __restrict__ proj_b,
    const float* __restrict__ mlp_w, const float* __restrict__ mlp_b,
    const float* __restrict__ dense_w, const float* __restrict__ dense_b,
    float* __restrict__ out)
{
    int b = blockIdx.x, tid = threadIdx.x, lane = tid & 31, wid = tid >> 5;
    __shared__ float s_aw[EE];
    __shared__ float s_sc[LL];
    __shared__ float smax[16], ssum[16];
    __shared__ float s_v[EE], s_v2[EE];
    const float* kxb = g_kx + (size_t)b * LL * EE;
    if (tid < EE) s_aw[tid] = attn_w[tid];
    __syncthreads();
    float qd = g_qdot[b];
    for (int l = wid; l < LL; l += 16) {
        const float* row = kxb + (size_t)l * EE;
        float acc = 0.f;
        for (int e = lane; e < EE; e += 32) acc += row[e] * s_aw[e];
        #pragma unroll
        for (int o = 16; o > 0; o >>= 1) acc += __shfl_xor_sync(0xffffffffu, acc, o);
        if (lane == 0) s_sc[l] = tanhf(acc + qd);
    }
    __syncthreads();
    float x = s_sc[tid];
    float m = x;
    #pragma unroll
    for (int o = 16; o > 0; o >>= 1) m = fmaxf(m, __shfl_xor_sync(0xffffffffu, m, o));
    if (lane == 0) smax[wid] = m;
    __syncthreads();
    float bm = smax[0];
    #pragma unroll
    for (int w = 1; w < 16; w++) bm = fmaxf(bm, smax[w]);
    float p = expf(x - bm);
    float sm = p;
    #pragma unroll
    for (int o = 16; o > 0; o >>= 1) sm += __shfl_xor_sync(0xffffffffu, sm, o);
    if (lane == 0) ssum[wid] = sm;
    __syncthreads();
    float tot = 0.f;
    #pragma unroll
    for (int w = 0; w < 16; w++) tot += ssum[w];
    s_sc[tid] = p / tot;
    __syncthreads();
    if (tid < EE) {
        float acc = 0.f;
        for (int l = 0; l < LL; l++) acc += s_sc[l] * kxb[(size_t)l * EE + tid];
        s_v[tid] = acc;
    }
    __syncthreads();
    if (tid < EE) {
        float acc = proj_b[tid];
        const float* w = proj_w + (size_t)tid * EE;
        for (int e = 0; e < EE; e++) acc += s_v[e] * w[e];
        s_v2[tid] = acc + g_vs[b * EE + tid];
    }
    __syncthreads();
    if (tid < EE) {
        float acc = mlp_b[tid];
        const float* w = mlp_w + (size_t)tid * EE;
        for (int e = 0; e < EE; e++) acc += s_v2[e] * w[e];
        s_v[tid] = tanhf(acc);
    }
    __syncthreads();
    if (wid < 3) {
        const float* w = dense_w + (size_t)wid * EE;
        float acc = 0.f;
        for (int e = lane; e < EE; e += 32) acc += s_v[e] * w[e];
        #pragma unroll
        for (int o = 16; o > 0; o >>= 1) acc += __shfl_xor_sync(0xffffffffu, acc, o);
        if (lane == 0) out[b * 3 + wid] = acc + dense_b[wid];
    }
}

extern "C" void kernel_launch(void* const* d_in, const int* in_sizes, int n_in,
                              void* d_out, int out_size)
{
    const int*   text  = (const int*)d_in[0];
    const int*   aspi  = (const int*)d_in[1];
    const int*   xl    = (const int*)d_in[2];
    const int*   xr    = (const int*)d_in[3];
    const float* emb   = (const float*)d_in[4];
    const float* emb_a = (const float*)d_in[5];
    const float* Wih_l = (const float*)d_in[6];
    const float* Whh_l = (const float*)d_in[7];
    const float* bih_l = (const float*)d_in[8];
    const float* bhh_l = (const float*)d_in[9];
    const float* Wih_r = (const float*)d_in[10];
    const float* Whh_r = (const float*)d_in[11];
    const float* bih_r = (const float*)d_in[12];
    const float* bhh_r = (const float*)d_in[13];
    const float* mlw_l = (const float*)d_in[14];
    const float* mlb_l = (const float*)d_in[15];
    const float* mlw_r = (const float*)d_in[16];
    const float* mlb_r = (const float*)d_in[17];
    const float* w_k   = (const float*)d_in[18];
    const float* b_k   = (const float*)d_in[19];
    const float* w_q   = (const float*)d_in[20];
    const float* b_q   = (const float*)d_in[21];
    const float* aw    = (const float*)d_in[22];
    const float* pw    = (const float*)d_in[23];
    const float* pb    = (const float*)d_in[24];
    const float* mw    = (const float*)d_in[25];
    const float* mb    = (const float*)d_in[26];
    const float* dw    = (const float*)d_in[27];
    const float* db    = (const float*)d_in[28];
    float* out = (float*)d_out;

    k_wtb<<<dim3(G3, 2), 150>>>(Whh_l, Whh_r);
    k_init<<<BB, 512>>>(text, aspi, xl, xr, emb_a, w_q, b_q, aw, mlb_l, mlb_r);
    k_sort<<<1, 256>>>();

    dim3 gx((G3 + 63) / 64, LL / 64, BB);
    k_gemm<<<gx, 256>>>(emb, xl, Wih_l, bih_l, G3, 0, 1);
    k_gemm<<<gx, 256>>>(emb, xr, Wih_r, bih_r, G3, 1, 2);

    k_gru4<<<BB, 480>>>(bhh_l, bhh_r, mlw_l, mlb_l, mlw_r, mlb_r);

    k_mem<<<dim3(LL, BB), 320>>>(text, emb);
    k_vs<<<BB, 320>>>();

    dim3 gk((EE + 63) / 64, LL / 64, BB);
    k_gemm<<<gk, 256>>>(emb, (const int*)0, w_k, b_k, EE, 2, 0);

    k_tail<<<BB, 512>>>(aw, pw, pb, mw, mb, dw, db, out);
}

// round 7
// speedup vs baseline: 4.7284x; 1.0769x over previous
#include <cuda_runtime.h>
#include <cuda_bf16.h>
#include <math.h>

#define BB 128
#define LL 512
#define LAa 8
#define EE 300
#define HH 300
#define G3 900

__device__ __align__(16) int   g_mem_len[BB];
__device__ __align__(16) int   g_asp_len[BB];
__device__ __align__(16) int   g_left_len[BB];
__device__ __align__(16) int   g_right_len[BB];
__device__ __align__(16) int   g_order_l[BB];
__device__ __align__(16) int   g_order_r[BB];
__device__ __align__(16) float g_qdot[BB];
__device__ __align__(16) float g_attn_l[BB * LL];
__device__ __align__(16) float g_attn_r[BB * LL];
// Wtb[k2*900+g] = bf162( Whh[g][2k2], Whh[g][2k2+1] )
__device__ __align__(16) __nv_bfloat162 g_Wtb_l[150 * G3];
__device__ __align__(16) __nv_bfloat162 g_Wtb_r[150 * G3];
__device__ __align__(16) float g_xp_l[(size_t)BB * LL * G3];
__device__ __align__(16) float g_xp_r[(size_t)BB * LL * G3];
__device__ __align__(16) float g_memory[(size_t)BB * LL * EE];
__device__ __align__(16) float g_kx[(size_t)BB * LL * EE];
__device__ __align__(16) float g_vs[BB * EE];

__device__ __forceinline__ float sigf(float x) { return 1.0f / (1.0f + expf(-x)); }
// Fast gate math (GRU only): MUFU.TANH, 1 MUFU each.
__device__ __forceinline__ float ftanh(float x) {
    float y; asm("tanh.approx.f32 %0, %1;" : "=f"(y) : "f"(x)); return y;
}
__device__ __forceinline__ float fsig(float x) { return 0.5f * ftanh(0.5f * x) + 0.5f; }

// ---------------- K_wtb: pack W_hh into k-paired bf16 gate-major layout -------
__global__ void k_wtb(const float* __restrict__ Whh_l, const float* __restrict__ Whh_r)
{
    int g = blockIdx.x, side = blockIdx.y, k2 = threadIdx.x;   // k2 in [0,150)
    const float* W = side ? Whh_r : Whh_l;
    __nv_bfloat162* Wt = side ? g_Wtb_r : g_Wtb_l;
    float v0 = W[(size_t)g * HH + 2 * k2];
    float v1 = W[(size_t)g * HH + 2 * k2 + 1];
    Wt[(size_t)k2 * G3 + g] = __floats2bfloat162_rn(v0, v1);
}

// ---------------- K0: lengths, attn defaults, aspect mean -> qdot -------------
__global__ void k_init(const int* __restrict__ text, const int* __restrict__ aspi,
                       const int* __restrict__ xl, const int* __restrict__ xr,
                       const float* __restrict__ emb_aspect,
                       const float* __restrict__ w_q, const float* __restrict__ b_q,
                       const float* __restrict__ attn_w,
                       const float* __restrict__ mlp_l_b, const float* __restrict__ mlp_r_b)
{
    int b = blockIdx.x, tid = threadIdx.x;
    int ml = __syncthreads_count(text[b * LL + tid] != 0);
    int ll = __syncthreads_count(xl[b * LL + tid] != 0);
    int rl = __syncthreads_count(xr[b * LL + tid] != 0);
    int al = __syncthreads_count((tid < LAa) && (aspi[b * LAa + tid] != 0));
    if (tid == 0) { g_mem_len[b] = ml; g_left_len[b] = ll; g_right_len[b] = rl; g_asp_len[b] = al; }
    g_attn_l[b * LL + tid] = sigf(mlp_l_b[0]) + 0.5f;
    g_attn_r[b * LL + tid] = sigf(mlp_r_b[0]) + 0.5f;

    __shared__ float s_asp[EE];
    __shared__ float sred[16];
    if (tid < EE) {
        float acc = 0.f;
        #pragma unroll
        for (int a = 0; a < LAa; a++)
            if (a < al) acc += emb_aspect[(size_t)aspi[b * LAa + a] * EE + tid];
        s_asp[tid] = acc / (float)al;
    }
    __syncthreads();
    float val = 0.f;
    if (tid < EE) {
        float acc = b_q[tid];
        const float* wq = w_q + (size_t)tid * EE;
        for (int e = 0; e < EE; e++) acc += s_asp[e] * wq[e];
        val = acc * attn_w[EE + tid];
    }
    #pragma unroll
    for (int o = 16; o > 0; o >>= 1) val += __shfl_xor_sync(0xffffffffu, val, o);
    if ((tid & 31) == 0) sred[tid >> 5] = val;
    __syncthreads();
    if (tid == 0) {
        float s = 0.f;
        #pragma unroll
        for (int w = 0; w < 16; w++) s += sred[w];
        g_qdot[b] = s;
    }
}

// ---------------- K_sort: rank-sort sequence lengths (desc) per side ----------
__global__ void k_sort()
{
    int tid = threadIdx.x;            // 256 threads
    int side = tid >> 7, i = tid & 127;
    const int* lens = side ? g_right_len : g_left_len;
    int* ord = side ? g_order_r : g_order_l;
    int li = lens[i], r = 0;
    for (int j = 0; j < BB; j++) {
        int lj = lens[j];
        r += (lj > li) || (lj == li && j < i);
    }
    ord[r] = i;
}

// ---------------- K1: GEMM v2 — 128x64 tile, 8x4 per-thread -------------------
// C[b,m,n] = Arow(b,m).W[n] + bias[n];  Arow = emb[ids[b][m]] or g_memory[b][m]
__global__ void __launch_bounds__(256) k_gemm2(
    const float* __restrict__ Aext, const int* __restrict__ ids,
    const float* __restrict__ W, const float* __restrict__ bias,
    int N, int dst_sel, int limit_sel)
{
    const int K = EE;
    int b = blockIdx.z, m0 = blockIdx.y * 128, n0 = blockIdx.x * 64;
    int lim = (limit_sel == 1) ? g_left_len[b] : (limit_sel == 2) ? g_right_len[b] : LL;
    if (m0 >= lim) return;

    float* C = (dst_sel == 0) ? g_xp_l : (dst_sel == 1) ? g_xp_r : g_kx;
    float* Cb = C + (size_t)b * LL * N;
    const int* bids = ids ? (ids + (size_t)b * LL) : (const int*)0;

    __shared__ float As[16][128];
    __shared__ float Bs[16][64];

    int tid = threadIdx.x;
    int tx = tid & 15, ty = tid >> 4;        // compute: rows ty*8.., cols tx*4..
    int ar = tid >> 1, ac = (tid & 1) * 8;   // A load: row ar, k-offsets ac, ac+4
    int br = tid >> 2, bc = (tid & 3) * 4;   // B load: row br, k-offset bc

    int gm = m0 + ar;
    const float* arow;
    if (bids) arow = Aext + (size_t)bids[gm] * K;
    else      arow = g_memory + ((size_t)b * LL + gm) * K;
    int gn = n0 + br;
    const float* brow = (gn < N) ? (W + (size_t)gn * K) : (const float*)0;

    float acc[8][4];
    #pragma unroll
    for (int i = 0; i < 8; i++)
        #pragma unroll
        for (int j = 0; j < 4; j++) acc[i][j] = 0.f;

    for (int k0 = 0; k0 < K; k0 += 16) {
        float4 av0 = make_float4(0.f, 0.f, 0.f, 0.f);
        float4 av1 = make_float4(0.f, 0.f, 0.f, 0.f);
        float4 bv  = make_float4(0.f, 0.f, 0.f, 0.f);
        if (k0 + ac < K)     av0 = *(const float4*)(arow + k0 + ac);
        if (k0 + ac + 4 < K) av1 = *(const float4*)(arow + k0 + ac + 4);
        if (brow && (k0 + bc < K)) bv = *(const float4*)(brow + k0 + bc);
        __syncthreads();
        As[ac + 0][ar] = av0.x; As[ac + 1][ar] = av0.y;
        As[ac + 2][ar] = av0.z; As[ac + 3][ar] = av0.w;
        As[ac + 4][ar] = av1.x; As[ac + 5][ar] = av1.y;
        As[ac + 6][ar] = av1.z; As[ac + 7][ar] = av1.w;
        Bs[bc + 0][br] = bv.x; Bs[bc + 1][br] = bv.y;
        Bs[bc + 2][br] = bv.z; Bs[bc + 3][br] = bv.w;
        __syncthreads();
        #pragma unroll
        for (int kk = 0; kk < 16; kk++) {
            float4 a0 = *(const float4*)&As[kk][ty * 8];
            float4 a1 = *(const float4*)&As[kk][ty * 8 + 4];
            float4 bb = *(const float4*)&Bs[kk][tx * 4];
            float av[8] = {a0.x, a0.y, a0.z, a0.w, a1.x, a1.y, a1.z, a1.w};
            #pragma unroll
            for (int i = 0; i < 8; i++) {
                acc[i][0] = fmaf(av[i], bb.x, acc[i][0]);
                acc[i][1] = fmaf(av[i], bb.y, acc[i][1]);
                acc[i][2] = fmaf(av[i], bb.z, acc[i][2]);
                acc[i][3] = fmaf(av[i], bb.w, acc[i][3]);
            }
        }
    }
    #pragma unroll
    for (int i = 0; i < 8; i++) {
        int om = m0 + ty * 8 + i;
        #pragma unroll
        for (int j = 0; j < 4; j++) {
            int on = n0 + tx * 4 + j;
            if (on < N) Cb[(size_t)om * N + on] = acc[i][j] + bias[on];
        }
    }
}

// ---------------- K2: GRU v4 — bf16 weights + fast gate math ------------------
__global__ void __launch_bounds__(480, 1) k_gru4(
    const float* __restrict__ bhh_l, const float* __restrict__ bhh_r,
    const float* __restrict__ mlpw_l, const float* __restrict__ mlpb_l,
    const float* __restrict__ mlpw_r, const float* __restrict__ mlpb_r)
{
    int side = (blockIdx.x >= 64);
    int pb = blockIdx.x & 63;
    const __nv_bfloat162* Wt = side ? g_Wtb_r : g_Wtb_l;
    const float* bhh  = side ? bhh_r : bhh_l;
    const float* mlpw = side ? mlpw_r : mlpw_l;
    float mbb         = side ? mlpb_r[0] : mlpb_l[0];
    const float* xp   = side ? g_xp_r : g_xp_l;
    const int* lens   = side ? g_right_len : g_left_len;
    const int* ord    = side ? g_order_r : g_order_l;
    float* attn       = side ? g_attn_r : g_attn_l;

    int sA = ord[pb], sB = ord[127 - pb];
    int lenA = lens[sA], lenB = lens[sB];   // lenA >= lenB

    int tid = threadIdx.x, lane = tid & 31, wid = tid >> 5;

    __shared__ __align__(16) float2 s_h[EE];
    __shared__ float  s_part[2][2][G3];     // [kgroup][seq][gate]
    __shared__ float  parts[2][10];

    bool pa = (tid < 450);
    int grp = (tid >= 225) ? 1 : 0;
    int idx = tid - grp * 225;
    const uint4* Wbase = ((const uint4*)Wt) + grp * (75 * 225) + idx;

    float wm = 0.f, bhr = 0.f, bhz = 0.f, bhn = 0.f;
    if (tid < EE) {
        wm = mlpw[tid];
        bhr = bhh[tid]; bhz = bhh[HH + tid]; bhn = bhh[2 * HH + tid];
        s_h[tid] = make_float2(0.f, 0.f);
    }
    const float* xpA = xp + (size_t)sA * LL * G3;
    const float* xpB = xp + (size_t)sB * LL * G3;
    __syncthreads();

    for (int t = 0; t < lenA; t++) {
        bool aB = (t < lenB);
        float gA0 = 0.f, gA1 = 0.f, gA2 = 0.f, gB0 = 0.f, gB1 = 0.f, gB2 = 0.f;
        if (tid < EE) {
            const float* g = xpA + (size_t)t * G3;
            gA0 = g[tid]; gA1 = g[HH + tid]; gA2 = g[2 * HH + tid];
            if (aB) {
                const float* h = xpB + (size_t)t * G3;
                gB0 = h[tid]; gB1 = h[HH + tid]; gB2 = h[2 * HH + tid];
            }
        }
        if (pa) {
            const uint4* wp = Wbase;
            const float4* hp = ((const float4*)s_h) + grp * 75;
            float a0 = 0.f, a1 = 0.f, a2 = 0.f, a3 = 0.f;
            float b0 = 0.f, b1 = 0.f, b2 = 0.f, b3 = 0.f;
            if (aB) {
                #pragma unroll 5
                for (int k = 0; k < 75; k++) {
                    uint4 w = *wp; wp += 225;
                    float4 h = hp[k];
                    float w0a = __int_as_float(w.x << 16), w0b = __int_as_float(w.x & 0xffff0000u);
                    float w1a = __int_as_float(w.y << 16), w1b = __int_as_float(w.y & 0xffff0000u);
                    float w2a = __int_as_float(w.z << 16), w2b = __int_as_float(w.z & 0xffff0000u);
                    float w3a = __int_as_float(w.w << 16), w3b = __int_as_float(w.w & 0xffff0000u);
                    a0 = fmaf(w0a, h.x, a0); a0 = fmaf(w0b, h.z, a0);
                    a1 = fmaf(w1a, h.x, a1); a1 = fmaf(w1b, h.z, a1);
                    a2 = fmaf(w2a, h.x, a2); a2 = fmaf(w2b, h.z, a2);
                    a3 = fmaf(w3a, h.x, a3); a3 = fmaf(w3b, h.z, a3);
                    b0 = fmaf(w0a, h.y, b0); b0 = fmaf(w0b, h.w, b0);
                    b1 = fmaf(w1a, h.y, b1); b1 = fmaf(w1b, h.w, b1);
                    b2 = fmaf(w2a, h.y, b2); b2 = fmaf(w2b, h.w, b2);
                    b3 = fmaf(w3a, h.y, b3); b3 = fmaf(w3b, h.w, b3);
                }
                *(float4*)&s_part[grp][1][idx * 4] = make_float4(b0, b1, b2, b3);
            } else {
                #pragma unroll 5
                for (int k = 0; k < 75; k++) {
                    uint4 w = *wp; wp += 225;
                    float4 h = hp[k];
                    float w0a = __int_as_float(w.x << 16), w0b = __int_as_float(w.x & 0xffff0000u);
                    float w1a = __int_as_float(w.y << 16), w1b = __int_as_float(w.y & 0xffff0000u);
                    float w2a = __int_as_float(w.z << 16), w2b = __int_as_float(w.z & 0xffff0000u);
                    float w3a = __int_as_float(w.w << 16), w3b = __int_as_float(w.w & 0xffff0000u);
                    a0 = fmaf(w0a, h.x, a0); a0 = fmaf(w0b, h.z, a0);
                    a1 = fmaf(w1a, h.x, a1); a1 = fmaf(w1b, h.z, a1);
                    a2 = fmaf(w2a, h.x, a2); a2 = fmaf(w2b, h.z, a2);
                    a3 = fmaf(w3a, h.x, a3); a3 = fmaf(w3b, h.z, a3);
                }
            }
            *(float4*)&s_part[grp][0][idx * 4] = make_float4(a0, a1, a2, a3);
        }
        __syncthreads();
        float vA = 0.f, vB = 0.f;
        if (tid < EE) {
            float2 h = s_h[tid];
            {
                float rp = s_part[0][0][tid] + s_part[1][0][tid];
                float zp = s_part[0][0][HH + tid] + s_part[1][0][HH + tid];
                float np = s_part[0][0][2 * HH + tid] + s_part[1][0][2 * HH + tid];
                float r = fsig(gA0 + rp + bhr);
                float z = fsig(gA1 + zp + bhz);
                float n = ftanh(gA2 + r * (np + bhn));
                h.x = (1.f - z) * n + z * h.x;
                vA = h.x * wm;
            }
            if (aB) {
                float rp = s_part[0][1][tid] + s_part[1][1][tid];
                float zp = s_part[0][1][HH + tid] + s_part[1][1][HH + tid];
                float np = s_part[0][1][2 * HH + tid] + s_part[1][1][2 * HH + tid];
                float r = fsig(gB0 + rp + bhr);
                float z = fsig(gB1 + zp + bhz);
                float n = ftanh(gB2 + r * (np + bhn));
                h.y = (1.f - z) * n + z * h.y;
                vB = h.y * wm;
            }
            s_h[tid] = h;
        }
        #pragma unroll
        for (int o = 16; o > 0; o >>= 1) {
            vA += __shfl_xor_sync(0xffffffffu, vA, o);
            vB += __shfl_xor_sync(0xffffffffu, vB, o);
        }
        if (lane == 0 && wid < 10) { parts[0][wid] = vA; parts[1][wid] = vB; }
        __syncthreads();
        if (tid == 0) {
            float s = 0.f;
            #pragma unroll
            for (int w = 0; w < 10; w++) s += parts[0][w];
            attn[sA * LL + t] = fsig(s + mbb) + 0.5f;
        }
        if (tid == 32 && aB) {
            float s = 0.f;
            #pragma unroll
            for (int w = 0; w < 10; w++) s += parts[1][w];
            attn[sB * LL + t] = fsig(s + mbb) + 0.5f;
        }
    }
}

// ---------------- K3: memory = emb[text] * scale ------------------------------
__global__ void k_mem(const int* __restrict__ text, const float* __restrict__ emb)
{
    int l = blockIdx.x, b = blockIdx.y, tid = threadIdx.x;
    if (tid >= EE) return;
    float* row = g_memory + ((size_t)b * LL + l) * EE;
    int ml = g_mem_len[b];
    if (l >= ml) { row[tid] = 0.f; return; }
    int astart = g_left_len[b] - g_asp_len[b];
    int aend = g_left_len[b];
    float al = g_attn_l[b * LL + l];
    int ridx = min(max(l - astart, 0), LL - 1);
    float arv = g_attn_r[b * LL + ridx];
    float sc = (l < astart) ? al : ((l < aend) ? (al + arv) : arv);
    int id = text[b * LL + l];
    row[tid] = emb[(size_t)id * EE + tid] * sc;
}

// ---------------- K4: v_s -----------------------------------------------------
__global__ void k_vs()
{
    int b = blockIdx.x, tid = threadIdx.x;
    if (tid >= EE) return;
    float acc = 0.f;
    const float* p = g_memory + (size_t)b * LL * EE + tid;
    for (int l = 0; l < LL; l++) acc += p[(size_t)l * EE];
    g_vs[b * EE + tid] = acc / (float)g_mem_len[b];
}

// ---------------- K5: score->softmax->v_ts->proj->mlp->dense ------------------
__global__ void __launch_bounds__(512) k_tail(
    const float* __restrict__ attn_w,
    const float* __restrict__ proj_w, const float* __restrict__ proj_b,
    const float* __restrict__ mlp_w, const float* __restrict__ mlp_b,
    const float* __restrict__ dense_w, const float* __restrict__ dense_b,
    float* __restrict__ out)
{
    int b = blockIdx.x, tid = threadIdx.x, lane = tid & 31, wid = tid >> 5;
    __shared__ float s_aw[EE];
    __shared__ float s_sc[LL];
    __shared__ float smax[16], ssum[16];
    __shared__ float s_v[EE], s_v2[EE];
    const float* kxb = g_kx + (size_t)b * LL * EE;
    if (tid < EE) s_aw[tid] = attn_w[tid];
    __syncthreads();
    float qd = g_qdot[b];
    for (int l = wid; l < LL; l += 16) {
        const float* row = kxb + (size_t)l * EE;
        float acc = 0.f;
        for (int e = lane; e < EE; e += 32) acc += row[e] * s_aw[e];
        #pragma unroll
        for (int o = 16; o > 0; o >>= 1) acc += __shfl_xor_sync(0xffffffffu, acc, o);
        if (lane == 0) s_sc[l] = tanhf(acc + qd);
    }
    __syncthreads();
    float x = s_sc[tid];
    float m = x;
    #pragma unroll
    for (int o = 16; o > 0; o >>= 1) m = fmaxf(m, __shfl_xor_sync(0xffffffffu, m, o));
    if (lane == 0) smax[wid] = m;
    __syncthreads();
    float bm = smax[0];
    #pragma unroll
    for (int w = 1; w < 16; w++) bm = fmaxf(bm, smax[w]);
    float p = expf(x - bm);
    float sm = p;
    #pragma unroll
    for (int o = 16; o > 0; o >>= 1) sm += __shfl_xor_sync(0xffffffffu, sm, o);
    if (lane == 0) ssum[wid] = sm;
    __syncthreads();
    float tot = 0.f;
    #pragma unroll
    for (int w = 0; w < 16; w++) tot += ssum[w];
    s_sc[tid] = p / tot;
    __syncthreads();
    if (tid < EE) {
        float acc = 0.f;
        for (int l = 0; l < LL; l++) acc += s_sc[l] * kxb[(size_t)l * EE + tid];
        s_v[tid] = acc;
    }
    __syncthreads();
    if (tid < EE) {
        float acc = proj_b[tid];
        const float* w = proj_w + (size_t)tid * EE;
        for (int e = 0; e < EE; e++) acc += s_v[e] * w[e];
        s_v2[tid] = acc + g_vs[b * EE + tid];
    }
    __syncthreads();
    if (tid < EE) {
        float acc = mlp_b[tid];
        const float* w = mlp_w + (size_t)tid * EE;
        for (int e = 0; e < EE; e++) acc += s_v2[e] * w[e];
        s_v[tid] = tanhf(acc);
    }
    __syncthreads();
    if (wid < 3) {
        const float* w = dense_w + (size_t)wid * EE;
        float acc = 0.f;
        for (int e = lane; e < EE; e += 32) acc += s_v[e] * w[e];
        #pragma unroll
        for (int o = 16; o > 0; o >>= 1) acc += __shfl_xor_sync(0xffffffffu, acc, o);
        if (lane == 0) out[b * 3 + wid] = acc + dense_b[wid];
    }
}

extern "C" void kernel_launch(void* const* d_in, const int* in_sizes, int n_in,
                              void* d_out, int out_size)
{
    const int*   text  = (const int*)d_in[0];
    const int*   aspi  = (const int*)d_in[1];
    const int*   xl    = (const int*)d_in[2];
    const int*   xr    = (const int*)d_in[3];
    const float* emb   = (const float*)d_in[4];
    const float* emb_a = (const float*)d_in[5];
    const float* Wih_l = (const float*)d_in[6];
    const float* Whh_l = (const float*)d_in[7];
    const float* bih_l = (const float*)d_in[8];
    const float* bhh_l = (const float*)d_in[9];
    const float* Wih_r = (const float*)d_in[10];
    const float* Whh_r = (const float*)d_in[11];
    const float* bih_r = (const float*)d_in[12];
    const float* bhh_r = (const float*)d_in[13];
    const float* mlw_l = (const float*)d_in[14];
    const float* mlb_l = (const float*)d_in[15];
    const float* mlw_r = (const float*)d_in[16];
    const float* mlb_r = (const float*)d_in[17];
    const float* w_k   = (const float*)d_in[18];
    const float* b_k   = (const float*)d_in[19];
    const float* w_q   = (const float*)d_in[20];
    const float* b_q   = (const float*)d_in[21];
    const float* aw    = (const float*)d_in[22];
    const float* pw    = (const float*)d_in[23];
    const float* pb    = (const float*)d_in[24];
    const float* mw    = (const float*)d_in[25];
    const float* mb    = (const float*)d_in[26];
    const float* dw    = (const float*)d_in[27];
    const float* db    = (const float*)d_in[28];
    float* out = (float*)d_out;

    k_wtb<<<dim3(G3, 2), 150>>>(Whh_l, Whh_r);
    k_init<<<BB, 512>>>(text, aspi, xl, xr, emb_a, w_q, b_q, aw, mlb_l, mlb_r);
    k_sort<<<1, 256>>>();

    dim3 gx((G3 + 63) / 64, LL / 128, BB);
    k_gemm2<<<gx, 256>>>(emb, xl, Wih_l, bih_l, G3, 0, 1);
    k_gemm2<<<gx, 256>>>(emb, xr, Wih_r, bih_r, G3, 1, 2);

    k_gru4<<<BB, 480>>>(bhh_l, bhh_r, mlw_l, mlb_l, mlw_r, mlb_r);

    k_mem<<<dim3(LL, BB), 320>>>(text, emb);
    k_vs<<<BB, 320>>>();

    dim3 gk((EE + 63) / 64, LL / 128, BB);
    k_gemm2<<<gk, 256>>>(emb, (const int*)0, w_k, b_k, EE, 2, 0);

    k_tail<<<BB, 512>>>(aw, pw, pb, mw, mb, dw, db, out);
}

// round 8
// speedup vs baseline: 5.2111x; 1.1021x over previous
#include <cuda_runtime.h>
#include <cuda_bf16.h>
#include <math.h>

#define BB 128
#define LL 512
#define LAa 8
#define EE 300
#define HH 300
#define G3 900

__device__ __align__(16) int   g_mem_len[BB];
__device__ __align__(16) int   g_asp_len[BB];
__device__ __align__(16) int   g_left_len[BB];
__device__ __align__(16) int   g_right_len[BB];
__device__ __align__(16) float g_qdot[BB];
__device__ __align__(16) float g_attn_l[BB * LL];
__device__ __align__(16) float g_attn_r[BB * LL];
__device__ __align__(16) float g_xp_l[(size_t)BB * LL * G3];
__device__ __align__(16) float g_xp_r[(size_t)BB * LL * G3];
__device__ __align__(16) float g_memory[(size_t)BB * LL * EE];
__device__ __align__(16) float g_kx[(size_t)BB * LL * EE];
__device__ __align__(16) float g_vs[BB * EE];

// cluster-GRU schedule + packed weights
__device__ int   g_grp_seq[64][4];
__device__ int   g_grp_len[64][4];
__device__ int   g_grp_maxlen[64];
__device__ int   g_grp_side[64];
__device__ int   g_clu_grp[32][2];
__device__ float g_kpad;
// Wpk[(side*4+rank)*150*225 + k2*225 + row], row: gatetype*75+u, bf162(k=2k2, 2k2+1)
__device__ __align__(16) unsigned int g_Wpk[8 * 150 * 225];

__device__ __forceinline__ float sigf(float x) { return 1.0f / (1.0f + expf(-x)); }
__device__ __forceinline__ float ftanh(float x) {
    float y; asm("tanh.approx.f32 %0, %1;" : "=f"(y) : "f"(x)); return y;
}
__device__ __forceinline__ float fsig(float x) { return 0.5f * ftanh(0.5f * x) + 0.5f; }

__device__ __forceinline__ unsigned smem_u32(const void* p) {
    unsigned r;
    asm("{ .reg .u64 t; cvta.to.shared.u64 t, %1; cvt.u32.u64 %0, t; }" : "=r"(r) : "l"(p));
    return r;
}
__device__ __forceinline__ unsigned ctarank() {
    unsigned r; asm("mov.u32 %0, %%cluster_ctarank;" : "=r"(r)); return r;
}
#define CLUSTER_SYNC() do { \
    asm volatile("barrier.cluster.arrive.aligned;" ::: "memory"); \
    asm volatile("barrier.cluster.wait.aligned;" ::: "memory"); } while (0)

__device__ __forceinline__ void dst_f32(unsigned laddr, unsigned rk, float v) {
    asm volatile("{ .reg .b32 ra; mapa.shared::cluster.u32 ra, %0, %1; "
                 "st.shared::cluster.b32 [ra], %2; }"
                 :: "r"(laddr), "r"(rk), "r"(__float_as_uint(v)) : "memory");
}

// ---------------- K_wpk: pack W_hh for cluster layout -------------------------
__global__ void k_wpk(const float* __restrict__ Whh_l, const float* __restrict__ Whh_r)
{
    int row = blockIdx.x;     // 0..224
    int sr  = blockIdx.y;     // side*4+rank
    int k2  = threadIdx.x;    // 0..149
    int side = sr >> 2, rank = sr & 3;
    const float* W = side ? Whh_r : Whh_l;
    int gt = row / 75, u = row % 75;
    int G = gt * 300 + rank * 75 + u;
    __nv_bfloat162 p = __floats2bfloat162_rn(W[(size_t)G * HH + 2 * k2],
                                             W[(size_t)G * HH + 2 * k2 + 1]);
    g_Wpk[(size_t)(sr * 150 + k2) * 225 + row] = *(unsigned int*)&p;
}

// ---------------- K0: lengths, attn defaults, aspect mean -> qdot -------------
__global__ void k_init(const int* __restrict__ text, const int* __restrict__ aspi,
                       const int* __restrict__ xl, const int* __restrict__ xr,
                       const float* __restrict__ emb_aspect,
                       const float* __restrict__ w_q, const float* __restrict__ b_q,
                       const float* __restrict__ attn_w,
                       const float* __restrict__ mlp_l_b, const float* __restrict__ mlp_r_b)
{
    int b = blockIdx.x, tid = threadIdx.x;
    int ml = __syncthreads_count(text[b * LL + tid] != 0);
    int ll = __syncthreads_count(xl[b * LL + tid] != 0);
    int rl = __syncthreads_count(xr[b * LL + tid] != 0);
    int al = __syncthreads_count((tid < LAa) && (aspi[b * LAa + tid] != 0));
    if (tid == 0) { g_mem_len[b] = ml; g_left_len[b] = ll; g_right_len[b] = rl; g_asp_len[b] = al; }
    g_attn_l[b * LL + tid] = sigf(mlp_l_b[0]) + 0.5f;
    g_attn_r[b * LL + tid] = sigf(mlp_r_b[0]) + 0.5f;

    __shared__ float s_asp[EE];
    __shared__ float sred[16];
    if (tid < EE) {
        float acc = 0.f;
        #pragma unroll
        for (int a = 0; a < LAa; a++)
            if (a < al) acc += emb_aspect[(size_t)aspi[b * LAa + a] * EE + tid];
        s_asp[tid] = acc / (float)al;
    }
    __syncthreads();
    float val = 0.f;
    if (tid < EE) {
        float acc = b_q[tid];
        const float* wq = w_q + (size_t)tid * EE;
        for (int e = 0; e < EE; e++) acc += s_asp[e] * wq[e];
        val = acc * attn_w[EE + tid];
    }
    #pragma unroll
    for (int o = 16; o > 0; o >>= 1) val += __shfl_xor_sync(0xffffffffu, val, o);
    if ((tid & 31) == 0) sred[tid >> 5] = val;
    __syncthreads();
    if (tid == 0) {
        float s = 0.f;
        #pragma unroll
        for (int w = 0; w < 16; w++) s += sred[w];
        g_qdot[b] = s;
    }
}

// ---------------- K_sched: groups of 4 per side, snake over 32 clusters -------
__global__ void k_sched(const float* __restrict__ b_k, const float* __restrict__ attn_w)
{
    __shared__ float sred[256];
    int i = threadIdx.x;  // 256 threads, 1 block
    float p = 0.f;
    for (int e = i; e < EE; e += 256) p += b_k[e] * attn_w[e];
    sred[i] = p;
    __syncthreads();
    if (i == 0) { float s = 0.f; for (int m = 0; m < 256; m++) s += sred[m]; g_kpad = s; }

    int side = i >> 7, j = i & 127;
    const int* lens = side ? g_right_len : g_left_len;
    int lj = lens[j], r = 0;
    for (int m = 0; m < BB; m++) {
        int lm = lens[m];
        r += (lm > lj) || (lm == lj && m < j);
    }
    int g = side * 32 + (r >> 2);
    g_grp_seq[g][r & 3] = j;
    g_grp_len[g][r & 3] = lj;
    if ((r & 3) == 0) { g_grp_maxlen[g] = lj; g_grp_side[g] = side; }
    __syncthreads();
    if (i < 64) {
        int ml = g_grp_maxlen[i]; int r2 = 0;
        for (int m = 0; m < 64; m++) {
            int lm = g_grp_maxlen[m];
            r2 += (lm > ml) || (lm == ml && m < i);
        }
        int cl = (r2 < 32) ? r2 : 63 - r2;
        g_clu_grp[cl][(r2 < 32) ? 0 : 1] = i;
    }
}

// ---------------- K1: GEMM v2 — 128x64 tile, 8x4 per-thread -------------------
__global__ void __launch_bounds__(256) k_gemm2(
    const float* __restrict__ Aext, const int* __restrict__ ids,
    const float* __restrict__ W, const float* __restrict__ bias,
    int N, int dst_sel, int limit_sel)
{
    const int K = EE;
    int b = blockIdx.z, m0 = blockIdx.y * 128, n0 = blockIdx.x * 64;
    int lim = (limit_sel == 1) ? g_left_len[b] : (limit_sel == 2) ? g_right_len[b]
            : (limit_sel == 3) ? g_mem_len[b] : LL;
    if (m0 >= lim) return;

    float* C = (dst_sel == 0) ? g_xp_l : (dst_sel == 1) ? g_xp_r : g_kx;
    float* Cb = C + (size_t)b * LL * N;
    const int* bids = ids ? (ids + (size_t)b * LL) : (const int*)0;

    __shared__ float As[16][128];
    __shared__ float Bs[16][64];

    int tid = threadIdx.x;
    int tx = tid & 15, ty = tid >> 4;
    int ar = tid >> 1, ac = (tid & 1) * 8;
    int br = tid >> 2, bc = (tid & 3) * 4;

    int gm = m0 + ar;
    const float* arow;
    if (bids) arow = Aext + (size_t)bids[gm] * K;
    else      arow = g_memory + ((size_t)b * LL + gm) * K;
    int gn = n0 + br;
    const float* brow = (gn < N) ? (W + (size_t)gn * K) : (const float*)0;

    float acc[8][4];
    #pragma unroll
    for (int i = 0; i < 8; i++)
        #pragma unroll
        for (int j = 0; j < 4; j++) acc[i][j] = 0.f;

    for (int k0 = 0; k0 < K; k0 += 16) {
        float4 av0 = make_float4(0.f, 0.f, 0.f, 0.f);
        float4 av1 = make_float4(0.f, 0.f, 0.f, 0.f);
        float4 bv  = make_float4(0.f, 0.f, 0.f, 0.f);
        if (k0 + ac < K)     av0 = *(const float4*)(arow + k0 + ac);
        if (k0 + ac + 4 < K) av1 = *(const float4*)(arow + k0 + ac + 4);
        if (brow && (k0 + bc < K)) bv = *(const float4*)(brow + k0 + bc);
        __syncthreads();
        As[ac + 0][ar] = av0.x; As[ac + 1][ar] = av0.y;
        As[ac + 2][ar] = av0.z; As[ac + 3][ar] = av0.w;
        As[ac + 4][ar] = av1.x; As[ac + 5][ar] = av1.y;
        As[ac + 6][ar] = av1.z; As[ac + 7][ar] = av1.w;
        Bs[bc + 0][br] = bv.x; Bs[bc + 1][br] = bv.y;
        Bs[bc + 2][br] = bv.z; Bs[bc + 3][br] = bv.w;
        __syncthreads();
        #pragma unroll
        for (int kk = 0; kk < 16; kk++) {
            float4 a0 = *(const float4*)&As[kk][ty * 8];
            float4 a1 = *(const float4*)&As[kk][ty * 8 + 4];
            float4 bb = *(const float4*)&Bs[kk][tx * 4];
            float av[8] = {a0.x, a0.y, a0.z, a0.w, a1.x, a1.y, a1.z, a1.w};
            #pragma unroll
            for (int i = 0; i < 8; i++) {
                acc[i][0] = fmaf(av[i], bb.x, acc[i][0]);
                acc[i][1] = fmaf(av[i], bb.y, acc[i][1]);
                acc[i][2] = fmaf(av[i], bb.z, acc[i][2]);
                acc[i][3] = fmaf(av[i], bb.w, acc[i][3]);
            }
        }
    }
    #pragma unroll
    for (int i = 0; i < 8; i++) {
        int om = m0 + ty * 8 + i;
        #pragma unroll
        for (int j = 0; j < 4; j++) {
            int on = n0 + tx * 4 + j;
            if (on < N) Cb[(size_t)om * N + on] = acc[i][j] + bias[on];
        }
    }
}

// ---------------- K2: cluster-4 GRU, smem-resident bf16 weights ---------------
// 32 clusters x 4 CTAs. CTA rank owns units [75r,75r+75) (gates r/z/n).
// Each cluster runs 2 groups of 4 sequences (balanced schedule).
#define GRU_SMEM 153248
__global__ void __launch_bounds__(512, 1) __cluster_dims__(4, 1, 1)
k_gruC(const float* __restrict__ bhh_l, const float* __restrict__ bhh_r,
       const float* __restrict__ mlpw_l, const float* __restrict__ mlpb_l,
       const float* __restrict__ mlpw_r, const float* __restrict__ mlpb_r)
{
    extern __shared__ char smem[];
    unsigned int* sW = (unsigned int*)smem;                          // 135000 B
    float* s_h       = (float*)(smem + 135040);                      // 2*300*4 f
    float* s_part    = (float*)(smem + 135040 + 9600);               // 2*225*4 f
    float* s_red     = (float*)(smem + 135040 + 9600 + 7200);        // 4*80 f
    float* s_partial = (float*)(smem + 135040 + 9600 + 7200 + 1280); // 2*4*4 f

    int tid = threadIdx.x, lane = tid & 31, wid = tid >> 5;
    unsigned rank = ctarank();
    int c = blockIdx.x >> 2;

    for (int gi = 0; gi < 2; gi++) {
        int grp  = g_clu_grp[c][gi];
        int side = g_grp_side[grp];
        int tmax = g_grp_maxlen[grp];
        const float* bhh  = side ? bhh_r : bhh_l;
        const float* mlpw = side ? mlpw_r : mlpw_l;
        float mbb = side ? mlpb_r[0] : mlpb_l[0];
        const float* xp = side ? g_xp_r : g_xp_l;
        float* attn = side ? g_attn_r : g_attn_l;
        int seqv[4], lenv[4];
        #pragma unroll
        for (int s = 0; s < 4; s++) { seqv[s] = g_grp_seq[grp][s]; lenv[s] = g_grp_len[grp][s]; }

        const unsigned int* wsrc = g_Wpk + (size_t)(side * 4 + rank) * 33750;
        for (int idx = tid; idx < 33750; idx += 512) sW[idx] = wsrc[idx];
        for (int idx = tid; idx < 2400; idx += 512) s_h[idx] = 0.f;

        int sB = tid / 75, uB = tid % 75, GB = (int)rank * 75 + uB;
        float bhr = 0.f, bhz = 0.f, bhn = 0.f, wm = 0.f;
        const float* xpb = 0;
        if (tid < 300) {
            bhr = bhh[GB]; bhz = bhh[300 + GB]; bhn = bhh[600 + GB]; wm = mlpw[GB];
            xpb = xp + (size_t)seqv[sB] * LL * G3;
        }
        int grp2 = (tid >= 225) ? 1 : 0;
        int row = tid - grp2 * 225;
        const unsigned int* wp0 = sW + grp2 * 16875 + row;
        unsigned hlocal0 = 0, hlocal1 = 0;
        if (tid < 300) {
            hlocal0 = smem_u32(&s_h[GB * 4 + sB]);
            hlocal1 = smem_u32(&s_h[1200 + GB * 4 + sB]);
        }
        __syncthreads();
        CLUSTER_SYNC();

        int buf = 0;
        for (int t = 0; t < tmax; t++) {
            if (t > 0 && rank == 0 && tid < 4) {
                float* pp = s_partial + (buf ^ 1) * 16;
                float sum = pp[tid] + pp[4 + tid] + pp[8 + tid] + pp[12 + tid];
                if (t - 1 < lenv[tid]) attn[seqv[tid] * LL + (t - 1)] = fsig(sum + mbb) + 0.5f;
            }
            float gr = 0.f, gz = 0.f, gn2 = 0.f;
            if (tid < 300) {
                const float* xrow = xpb + (size_t)t * G3;
                gr = xrow[GB]; gz = xrow[300 + GB]; gn2 = xrow[600 + GB];
            }
            if (tid < 450) {
                const float4* hp = (const float4*)(s_h + buf * 1200) + grp2 * 150;
                float a0 = 0.f, a1 = 0.f, a2 = 0.f, a3 = 0.f;
                #pragma unroll 5
                for (int k2 = 0; k2 < 75; k2++) {
                    unsigned w = wp0[k2 * 225];
                    float wlo = __int_as_float(w << 16);
                    float whi = __int_as_float(w & 0xffff0000u);
                    float4 h0 = hp[2 * k2], h1 = hp[2 * k2 + 1];
                    a0 = fmaf(wlo, h0.x, a0); a0 = fmaf(whi, h1.x, a0);
                    a1 = fmaf(wlo, h0.y, a1); a1 = fmaf(whi, h1.y, a1);
                    a2 = fmaf(wlo, h0.z, a2); a2 = fmaf(whi, h1.z, a2);
                    a3 = fmaf(wlo, h0.w, a3); a3 = fmaf(whi, h1.w, a3);
                }
                *(float4*)&s_part[(grp2 * 225 + row) * 4] = make_float4(a0, a1, a2, a3);
            }
            __syncthreads();
            if (tid < 300) {
                float rp = s_part[uB * 4 + sB]          + s_part[(225 + uB) * 4 + sB];
                float zp = s_part[(75 + uB) * 4 + sB]   + s_part[(300 + uB) * 4 + sB];
                float np = s_part[(150 + uB) * 4 + sB]  + s_part[(375 + uB) * 4 + sB];
                float r = fsig(gr + rp + bhr);
                float z = fsig(gz + zp + bhz);
                float n = ftanh(gn2 + r * (np + bhn));
                float hold = s_h[buf * 1200 + GB * 4 + sB];
                float hn = (1.f - z) * n + z * hold;
                unsigned la = buf ? hlocal0 : hlocal1;
                #pragma unroll
                for (unsigned rk = 0; rk < 4; rk++) dst_f32(la, rk, hn);
                s_red[sB * 80 + uB] = hn * wm;
            }
            __syncthreads();
            if (wid < 4) {
                float v = s_red[wid * 80 + lane];
                if (lane < 43) v += s_red[wid * 80 + lane + 32];
                if (lane < 11) v += s_red[wid * 80 + lane + 64];
                #pragma unroll
                for (int o = 16; o > 0; o >>= 1) v += __shfl_xor_sync(0xffffffffu, v, o);
                if (lane == 0) {
                    unsigned la = smem_u32(&s_partial[buf * 16 + (int)rank * 4 + wid]);
                    dst_f32(la, 0, v);
                }
            }
            CLUSTER_SYNC();
            buf ^= 1;
        }
        if (rank == 0 && tid < 4) {
            float* pp = s_partial + (buf ^ 1) * 16;
            float sum = pp[tid] + pp[4 + tid] + pp[8 + tid] + pp[12 + tid];
            if (tmax - 1 < lenv[tid]) attn[seqv[tid] * LL + (tmax - 1)] = fsig(sum + mbb) + 0.5f;
        }
        __syncthreads();
    }
}

// ---------------- K3: memory = emb[text] * scale ------------------------------
__global__ void k_mem(const int* __restrict__ text, const float* __restrict__ emb)
{
    int l = blockIdx.x, b = blockIdx.y, tid = threadIdx.x;
    if (tid >= EE) return;
    float* row = g_memory + ((size_t)b * LL + l) * EE;
    int ml = g_mem_len[b];
    if (l >= ml) { row[tid] = 0.f; return; }
    int astart = g_left_len[b] - g_asp_len[b];
    int aend = g_left_len[b];
    float al = g_attn_l[b * LL + l];
    int ridx = min(max(l - astart, 0), LL - 1);
    float arv = g_attn_r[b * LL + ridx];
    float sc = (l < astart) ? al : ((l < aend) ? (al + arv) : arv);
    int id = text[b * LL + l];
    row[tid] = emb[(size_t)id * EE + tid] * sc;
}

// ---------------- K4: v_s -----------------------------------------------------
__global__ void k_vs()
{
    int b = blockIdx.x, tid = threadIdx.x;
    if (tid >= EE) return;
    float acc = 0.f;
    const float* p = g_memory + (size_t)b * LL * EE + tid;
    int ml = g_mem_len[b];
    for (int l = 0; l < ml; l++) acc += p[(size_t)l * EE];
    g_vs[b * EE + tid] = acc / (float)ml;
}

// ---------------- K5: score->softmax->v_ts->proj->mlp->dense ------------------
__global__ void __launch_bounds__(512) k_tail(
    const float* __restrict__ attn_w, const float* __restrict__ b_k,
    const float* __restrict__ proj_w, const float* __restrict__ proj_b,
    const float* __restrict__ mlp_w, const float* __restrict__ mlp_b,
    const float* __restrict__ dense_w, const float* __restrict__ dense_b,
    float* __restrict__ out)
{
    int b = blockIdx.x, tid = threadIdx.x, lane = tid & 31, wid = tid >> 5;
    __shared__ float s_aw[EE];
    __shared__ float s_sc[LL];
    __shared__ float smax[16], ssum[16];
    __shared__ float s_v[EE], s_v2[EE];
    const float* kxb = g_kx + (size_t)b * LL * EE;
    int ml = g_mem_len[b];
    if (tid < EE) s_aw[tid] = attn_w[tid];
    __syncthreads();
    float qd = g_qdot[b];
    float sc_pad = tanhf(g_kpad + qd);
    for (int l = wid; l < ml; l += 16) {
        const float* row = kxb + (size_t)l * EE;
        float acc = 0.f;
        for (int e = lane; e < EE; e += 32) acc += row[e] * s_aw[e];
        #pragma unroll
        for (int o = 16; o > 0; o >>= 1) acc += __shfl_xor_sync(0xffffffffu, acc, o);
        if (lane == 0) s_sc[l] = tanhf(acc + qd);
    }
    __syncthreads();
    float x = (tid < ml) ? s_sc[tid] : sc_pad;
    float m = x;
    #pragma unroll
    for (int o = 16; o > 0; o >>= 1) m = fmaxf(m, __shfl_xor_sync(0xffffffffu, m, o));
    if (lane == 0) smax[wid] = m;
    __syncthreads();
    float bm = smax[0];
    #pragma unroll
    for (int w = 1; w < 16; w++) bm = fmaxf(bm, smax[w]);
    float p = expf(x - bm);
    float sm = p;
    #pragma unroll
    for (int o = 16; o > 0; o >>= 1) sm += __shfl_xor_sync(0xffffffffu, sm, o);
    if (lane == 0) ssum[wid] = sm;
    __syncthreads();
    float tot = 0.f;
    #pragma unroll
    for (int w = 0; w < 16; w++) tot += ssum[w];
    s_sc[tid] = p / tot;
    __syncthreads();
    float pad_prob = expf(sc_pad - bm) / tot;
    if (tid < EE) {
        float acc = (float)(LL - ml) * pad_prob * b_k[tid];
        for (int l = 0; l < ml; l++) acc += s_sc[l] * kxb[(size_t)l * EE + tid];
        s_v[tid] = acc;
    }
    __syncthreads();
    if (tid < EE) {
        float acc = proj_b[tid];
        const float* w = proj_w + (size_t)tid * EE;
        for (int e = 0; e < EE; e++) acc += s_v[e] * w[e];
        s_v2[tid] = acc + g_vs[b * EE + tid];
    }
    __syncthreads();
    if (tid < EE) {
        float acc = mlp_b[tid];
        const float* w = mlp_w + (size_t)tid * EE;
        for (int e = 0; e < EE; e++) acc += s_v2[e] * w[e];
        s_v[tid] = tanhf(acc);
    }
    __syncthreads();
    if (wid < 3) {
        const float* w = dense_w + (size_t)wid * EE;
        float acc = 0.f;
        for (int e = lane; e < EE; e += 32) acc += s_v[e] * w[e];
        #pragma unroll
        for (int o = 16; o > 0; o >>= 1) acc += __shfl_xor_sync(0xffffffffu, acc, o);
        if (lane == 0) out[b * 3 + wid] = acc + dense_b[wid];
    }
}

extern "C" void kernel_launch(void* const* d_in, const int* in_sizes, int n_in,
                              void* d_out, int out_size)
{
    const int*   text  = (const int*)d_in[0];
    const int*   aspi  = (const int*)d_in[1];
    const int*   xl    = (const int*)d_in[2];
    const int*   xr    = (const int*)d_in[3];
    const float* emb   = (const float*)d_in[4];
    const float* emb_a = (const float*)d_in[5];
    const float* Wih_l = (const float*)d_in[6];
    const float* Whh_l = (const float*)d_in[7];
    const float* bih_l = (const float*)d_in[8];
    const float* bhh_l = (const float*)d_in[9];
    const float* Wih_r = (const float*)d_in[10];
    const float* Whh_r = (const float*)d_in[11];
    const float* bih_r = (const float*)d_in[12];
    const float* bhh_r = (const float*)d_in[13];
    const float* mlw_l = (const float*)d_in[14];
    const float* mlb_l = (const float*)d_in[15];
    const float* mlw_r = (const float*)d_in[16];
    const float* mlb_r = (const float*)d_in[17];
    const float* w_k   = (const float*)d_in[18];
    const float* b_k   = (const float*)d_in[19];
    const float* w_q   = (const float*)d_in[20];
    const float* b_q   = (const float*)d_in[21];
    const float* aw    = (const float*)d_in[22];
    const float* pw    = (const float*)d_in[23];
    const float* pb    = (const float*)d_in[24];
    const float* mw    = (const float*)d_in[25];
    const float* mb    = (const float*)d_in[26];
    const float* dw    = (const float*)d_in[27];
    const float* db    = (const float*)d_in[28];
    float* out = (float*)d_out;

    cudaFuncSetAttribute(k_gruC, cudaFuncAttributeMaxDynamicSharedMemorySize, GRU_SMEM);

    k_wpk<<<dim3(225, 8), 150>>>(Whh_l, Whh_r);
    k_init<<<BB, 512>>>(text, aspi, xl, xr, emb_a, w_q, b_q, aw, mlb_l, mlb_r);
    k_sched<<<1, 256>>>(b_k, aw);

    dim3 gx((G3 + 63) / 64, LL / 128, BB);
    k_gemm2<<<gx, 256>>>(emb, xl, Wih_l, bih_l, G3, 0, 1);
    k_gemm2<<<gx, 256>>>(emb, xr, Wih_r, bih_r, G3, 1, 2);

    k_gruC<<<BB, 512, GRU_SMEM>>>(bhh_l, bhh_r, mlw_l, mlb_l, mlw_r, mlb_r);

    k_mem<<<dim3(LL, BB), 320>>>(text, emb);
    k_vs<<<BB, 320>>>();

    dim3 gk((EE + 63) / 64, LL / 128, BB);
    k_gemm2<<<gk, 256>>>(emb, (const int*)0, w_k, b_k, EE, 2, 3);

    k_tail<<<BB, 512>>>(aw, b_k, pw, pb, mw, mb, dw, db, out);
}

// round 9
// speedup vs baseline: 5.8933x; 1.1309x over previous
#include <cuda_runtime.h>
#include <cuda_bf16.h>
#include <math.h>

#define BB 128
#define LL 512
#define LAa 8
#define EE 300
#define HH 300
#define G3 900

__device__ __align__(16) int   g_mem_len[BB];
__device__ __align__(16) int   g_asp_len[BB];
__device__ __align__(16) int   g_left_len[BB];
__device__ __align__(16) int   g_right_len[BB];
__device__ __align__(16) float g_qdot[BB];
__device__ __align__(16) float g_attn_l[BB * LL];
__device__ __align__(16) float g_attn_r[BB * LL];
__device__ __align__(16) float g_xp_l[(size_t)BB * LL * G3];
__device__ __align__(16) float g_xp_r[(size_t)BB * LL * G3];
__device__ __align__(16) float g_memory[(size_t)BB * LL * EE];
__device__ __align__(16) float g_kx[(size_t)BB * LL * EE];
__device__ __align__(16) float g_vs[BB * EE];

// cluster-GRU schedule + packed weights
__device__ int   g_grp_seq[64][4];
__device__ int   g_grp_len[64][4];
__device__ int   g_grp_maxlen[64];
__device__ int   g_grp_side[64];
__device__ int   g_clu_grp[32][2];
__device__ float g_kpad;
// Wpk[(side*4+rank)*150*225 + k2*225 + row], row: gatetype*75+u, bf162(k=2k2, 2k2+1)
__device__ __align__(16) unsigned int g_Wpk[8 * 150 * 225];

__device__ __forceinline__ float sigf(float x) { return 1.0f / (1.0f + expf(-x)); }
__device__ __forceinline__ float ftanh(float x) {
    float y; asm("tanh.approx.f32 %0, %1;" : "=f"(y) : "f"(x)); return y;
}
__device__ __forceinline__ float fsig(float x) { return 0.5f * ftanh(0.5f * x) + 0.5f; }

// ---- packed f32x2 helpers (sm_103a) ----
__device__ __forceinline__ unsigned long long pack2(float lo, float hi) {
    unsigned long long r;
    asm("mov.b64 %0, {%1, %2};" : "=l"(r) : "r"(__float_as_uint(lo)), "r"(__float_as_uint(hi)));
    return r;
}
__device__ __forceinline__ unsigned long long splat2(float v) { return pack2(v, v); }
__device__ __forceinline__ unsigned long long fma2(unsigned long long a, unsigned long long b,
                                                   unsigned long long c) {
    unsigned long long d;
    asm("fma.rn.f32x2 %0, %1, %2, %3;" : "=l"(d) : "l"(a), "l"(b), "l"(c));
    return d;
}
__device__ __forceinline__ float2 unpack2(unsigned long long v) {
    unsigned lo, hi;
    asm("mov.b64 {%0, %1}, %2;" : "=r"(lo), "=r"(hi) : "l"(v));
    return make_float2(__uint_as_float(lo), __uint_as_float(hi));
}

__device__ __forceinline__ unsigned smem_u32(const void* p) {
    unsigned r;
    asm("{ .reg .u64 t; cvta.to.shared.u64 t, %1; cvt.u32.u64 %0, t; }" : "=r"(r) : "l"(p));
    return r;
}
__device__ __forceinline__ unsigned ctarank() {
    unsigned r; asm("mov.u32 %0, %%cluster_ctarank;" : "=r"(r)); return r;
}
#define CLUSTER_SYNC() do { \
    asm volatile("barrier.cluster.arrive.aligned;" ::: "memory"); \
    asm volatile("barrier.cluster.wait.aligned;" ::: "memory"); } while (0)

__device__ __forceinline__ void dst_f32(unsigned laddr, unsigned rk, float v) {
    asm volatile("{ .reg .b32 ra; mapa.shared::cluster.u32 ra, %0, %1; "
                 "st.shared::cluster.b32 [ra], %2; }"
                 :: "r"(laddr), "r"(rk), "r"(__float_as_uint(v)) : "memory");
}

// ---------------- K_wpk: pack W_hh for cluster layout -------------------------
__global__ void k_wpk(const float* __restrict__ Whh_l, const float* __restrict__ Whh_r)
{
    int row = blockIdx.x;     // 0..224
    int sr  = blockIdx.y;     // side*4+rank
    int k2  = threadIdx.x;    // 0..149
    int side = sr >> 2, rank = sr & 3;
    const float* W = side ? Whh_r : Whh_l;
    int gt = row / 75, u = row % 75;
    int G = gt * 300 + rank * 75 + u;
    __nv_bfloat162 p = __floats2bfloat162_rn(W[(size_t)G * HH + 2 * k2],
                                             W[(size_t)G * HH + 2 * k2 + 1]);
    g_Wpk[(size_t)(sr * 150 + k2) * 225 + row] = *(unsigned int*)&p;
}

// ---------------- K0: lengths, attn defaults, aspect mean -> qdot -------------
__global__ void k_init(const int* __restrict__ text, const int* __restrict__ aspi,
                       const int* __restrict__ xl, const int* __restrict__ xr,
                       const float* __restrict__ emb_aspect,
                       const float* __restrict__ w_q, const float* __restrict__ b_q,
                       const float* __restrict__ attn_w,
                       const float* __restrict__ mlp_l_b, const float* __restrict__ mlp_r_b)
{
    int b = blockIdx.x, tid = threadIdx.x;
    int ml = __syncthreads_count(text[b * LL + tid] != 0);
    int ll = __syncthreads_count(xl[b * LL + tid] != 0);
    int rl = __syncthreads_count(xr[b * LL + tid] != 0);
    int al = __syncthreads_count((tid < LAa) && (aspi[b * LAa + tid] != 0));
    if (tid == 0) { g_mem_len[b] = ml; g_left_len[b] = ll; g_right_len[b] = rl; g_asp_len[b] = al; }
    g_attn_l[b * LL + tid] = sigf(mlp_l_b[0]) + 0.5f;
    g_attn_r[b * LL + tid] = sigf(mlp_r_b[0]) + 0.5f;

    __shared__ float s_asp[EE];
    __shared__ float sred[16];
    if (tid < EE) {
        float acc = 0.f;
        #pragma unroll
        for (int a = 0; a < LAa; a++)
            if (a < al) acc += emb_aspect[(size_t)aspi[b * LAa + a] * EE + tid];
        s_asp[tid] = acc / (float)al;
    }
    __syncthreads();
    float val = 0.f;
    if (tid < EE) {
        float acc = b_q[tid];
        const float* wq = w_q + (size_t)tid * EE;
        for (int e = 0; e < EE; e++) acc += s_asp[e] * wq[e];
        val = acc * attn_w[EE + tid];
    }
    #pragma unroll
    for (int o = 16; o > 0; o >>= 1) val += __shfl_xor_sync(0xffffffffu, val, o);
    if ((tid & 31) == 0) sred[tid >> 5] = val;
    __syncthreads();
    if (tid == 0) {
        float s = 0.f;
        #pragma unroll
        for (int w = 0; w < 16; w++) s += sred[w];
        g_qdot[b] = s;
    }
}

// ---------------- K_sched: groups of 4 per side, snake over 32 clusters -------
__global__ void k_sched(const float* __restrict__ b_k, const float* __restrict__ attn_w)
{
    __shared__ float sred[256];
    int i = threadIdx.x;  // 256 threads, 1 block
    float p = 0.f;
    for (int e = i; e < EE; e += 256) p += b_k[e] * attn_w[e];
    sred[i] = p;
    __syncthreads();
    if (i == 0) { float s = 0.f; for (int m = 0; m < 256; m++) s += sred[m]; g_kpad = s; }

    int side = i >> 7, j = i & 127;
    const int* lens = side ? g_right_len : g_left_len;
    int lj = lens[j], r = 0;
    for (int m = 0; m < BB; m++) {
        int lm = lens[m];
        r += (lm > lj) || (lm == lj && m < j);
    }
    int g = side * 32 + (r >> 2);
    g_grp_seq[g][r & 3] = j;
    g_grp_len[g][r & 3] = lj;
    if ((r & 3) == 0) { g_grp_maxlen[g] = lj; g_grp_side[g] = side; }
    __syncthreads();
    if (i < 64) {
        int ml = g_grp_maxlen[i]; int r2 = 0;
        for (int m = 0; m < 64; m++) {
            int lm = g_grp_maxlen[m];
            r2 += (lm > ml) || (lm == ml && m < i);
        }
        int cl = (r2 < 32) ? r2 : 63 - r2;
        g_clu_grp[cl][(r2 < 32) ? 0 : 1] = i;
    }
}

// ---------------- K1: GEMM v3 — 128x64 tile, 8x4 per-thread, FFMA2 ------------
__global__ void __launch_bounds__(256) k_gemm2(
    const float* __restrict__ Aext, const int* __restrict__ ids,
    const float* __restrict__ W, const float* __restrict__ bias,
    int N, int dst_sel, int limit_sel)
{
    const int K = EE;
    int b = blockIdx.z, m0 = blockIdx.y * 128, n0 = blockIdx.x * 64;
    int lim = (limit_sel == 1) ? g_left_len[b] : (limit_sel == 2) ? g_right_len[b]
            : (limit_sel == 3) ? g_mem_len[b] : LL;
    if (m0 >= lim) return;

    float* C = (dst_sel == 0) ? g_xp_l : (dst_sel == 1) ? g_xp_r : g_kx;
    float* Cb = C + (size_t)b * LL * N;
    const int* bids = ids ? (ids + (size_t)b * LL) : (const int*)0;

    __shared__ __align__(16) float As[16][128];
    __shared__ __align__(16) float Bs[16][64];

    int tid = threadIdx.x;
    int tx = tid & 15, ty = tid >> 4;
    int ar = tid >> 1, ac = (tid & 1) * 8;
    int br = tid >> 2, bc = (tid & 3) * 4;

    int gm = m0 + ar;
    const float* arow;
    if (bids) arow = Aext + (size_t)bids[gm] * K;
    else      arow = g_memory + ((size_t)b * LL + gm) * K;
    int gn = n0 + br;
    const float* brow = (gn < N) ? (W + (size_t)gn * K) : (const float*)0;

    unsigned long long acc01[8], acc23[8];
    #pragma unroll
    for (int i = 0; i < 8; i++) { acc01[i] = 0ull; acc23[i] = 0ull; }

    for (int k0 = 0; k0 < K; k0 += 16) {
        float4 av0 = make_float4(0.f, 0.f, 0.f, 0.f);
        float4 av1 = make_float4(0.f, 0.f, 0.f, 0.f);
        float4 bv  = make_float4(0.f, 0.f, 0.f, 0.f);
        if (k0 + ac < K)     av0 = *(const float4*)(arow + k0 + ac);
        if (k0 + ac + 4 < K) av1 = *(const float4*)(arow + k0 + ac + 4);
        if (brow && (k0 + bc < K)) bv = *(const float4*)(brow + k0 + bc);
        __syncthreads();
        As[ac + 0][ar] = av0.x; As[ac + 1][ar] = av0.y;
        As[ac + 2][ar] = av0.z; As[ac + 3][ar] = av0.w;
        As[ac + 4][ar] = av1.x; As[ac + 5][ar] = av1.y;
        As[ac + 6][ar] = av1.z; As[ac + 7][ar] = av1.w;
        Bs[bc + 0][br] = bv.x; Bs[bc + 1][br] = bv.y;
        Bs[bc + 2][br] = bv.z; Bs[bc + 3][br] = bv.w;
        __syncthreads();
        #pragma unroll
        for (int kk = 0; kk < 16; kk++) {
            float4 a0 = *(const float4*)&As[kk][ty * 8];
            float4 a1 = *(const float4*)&As[kk][ty * 8 + 4];
            ulonglong2 bb2 = *(const ulonglong2*)&Bs[kk][tx * 4];
            float av[8] = {a0.x, a0.y, a0.z, a0.w, a1.x, a1.y, a1.z, a1.w};
            #pragma unroll
            for (int i = 0; i < 8; i++) {
                unsigned long long as = splat2(av[i]);
                acc01[i] = fma2(as, bb2.x, acc01[i]);
                acc23[i] = fma2(as, bb2.y, acc23[i]);
            }
        }
    }
    #pragma unroll
    for (int i = 0; i < 8; i++) {
        int om = m0 + ty * 8 + i;
        float2 p01 = unpack2(acc01[i]);
        float2 p23 = unpack2(acc23[i]);
        float vj[4] = {p01.x, p01.y, p23.x, p23.y};
        #pragma unroll
        for (int j = 0; j < 4; j++) {
            int on = n0 + tx * 4 + j;
            if (on < N) Cb[(size_t)om * N + on] = vj[j] + bias[on];
        }
    }
}

// ---------------- K2: cluster-4 GRU, register-resident bf16 weights, FFMA2 ----
// 32 clusters x 4 CTAs. CTA rank owns units [75r,75r+75) (gates r/z/n).
// Each cluster runs 2 groups of 4 sequences (balanced schedule).
__global__ void __launch_bounds__(512, 1) __cluster_dims__(4, 1, 1)
k_gruC(const float* __restrict__ bhh_l, const float* __restrict__ bhh_r,
       const float* __restrict__ mlpw_l, const float* __restrict__ mlpb_l,
       const float* __restrict__ mlpw_r, const float* __restrict__ mlpb_r)
{
    __shared__ __align__(16) float s_h[2 * 1200];     // [buf][k*4+seq]
    __shared__ __align__(16) float s_part[1800];      // [(grp2*225+row)*4+seq]
    __shared__ float s_red[320];
    __shared__ float s_partial[32];

    int tid = threadIdx.x, lane = tid & 31, wid = tid >> 5;
    unsigned rank = ctarank();
    int c = blockIdx.x >> 2;

    for (int gi = 0; gi < 2; gi++) {
        int grp  = g_clu_grp[c][gi];
        int side = g_grp_side[grp];
        int tmax = g_grp_maxlen[grp];
        const float* bhh  = side ? bhh_r : bhh_l;
        const float* mlpw = side ? mlpw_r : mlpw_l;
        float mbb = side ? mlpb_r[0] : mlpb_l[0];
        const float* xp = side ? g_xp_r : g_xp_l;
        float* attn = side ? g_attn_r : g_attn_l;
        int seqv[4], lenv[4];
        #pragma unroll
        for (int s = 0; s < 4; s++) { seqv[s] = g_grp_seq[grp][s]; lenv[s] = g_grp_len[grp][s]; }

        for (int idx = tid; idx < 2400; idx += 512) s_h[idx] = 0.f;

        int sB = tid / 75, uB = tid % 75, GB = (int)rank * 75 + uB;
        float bhr = 0.f, bhz = 0.f, bhn = 0.f, wm = 0.f;
        const float* xpb = 0;
        if (tid < 300) {
            bhr = bhh[GB]; bhz = bhh[300 + GB]; bhn = bhh[600 + GB]; wm = mlpw[GB];
            xpb = xp + (size_t)seqv[sB] * LL * G3;
        }
        int grp2 = (tid >= 225) ? 1 : 0;
        int row = tid - grp2 * 225;
        // register-resident weights (bf162 per k2)
        unsigned wreg[75];
        if (tid < 450) {
            const unsigned* wsrc = g_Wpk + (size_t)(side * 4 + (int)rank) * 33750
                                 + grp2 * 16875 + row;
            #pragma unroll
            for (int k2 = 0; k2 < 75; k2++) wreg[k2] = wsrc[k2 * 225];
        }
        unsigned hlocal0 = 0, hlocal1 = 0;
        if (tid < 300) {
            hlocal0 = smem_u32(&s_h[GB * 4 + sB]);
            hlocal1 = smem_u32(&s_h[1200 + GB * 4 + sB]);
        }
        __syncthreads();
        CLUSTER_SYNC();

        int buf = 0;
        for (int t = 0; t < tmax; t++) {
            if (t > 0 && rank == 0 && tid < 4) {
                float* pp = s_partial + (buf ^ 1) * 16;
                float sum = pp[tid] + pp[4 + tid] + pp[8 + tid] + pp[12 + tid];
                if (t - 1 < lenv[tid]) attn[seqv[tid] * LL + (t - 1)] = fsig(sum + mbb) + 0.5f;
            }
            float gr = 0.f, gz = 0.f, gn2 = 0.f;
            if (tid < 300) {
                const float* xrow = xpb + (size_t)t * G3;
                gr = xrow[GB]; gz = xrow[300 + GB]; gn2 = xrow[600 + GB];
            }
            if (tid < 450) {
                const ulonglong2* hp = (const ulonglong2*)(s_h + buf * 1200) + grp2 * 150;
                unsigned long long a01 = 0ull, a23 = 0ull;
                #pragma unroll
                for (int k2 = 0; k2 < 75; k2++) {
                    unsigned w = wreg[k2];
                    float wlo = __uint_as_float(w << 16);
                    float whi = __uint_as_float(w & 0xffff0000u);
                    unsigned long long wl2 = splat2(wlo);
                    unsigned long long wh2 = splat2(whi);
                    ulonglong2 h0 = hp[2 * k2];
                    ulonglong2 h1 = hp[2 * k2 + 1];
                    a01 = fma2(wl2, h0.x, a01);
                    a23 = fma2(wl2, h0.y, a23);
                    a01 = fma2(wh2, h1.x, a01);
                    a23 = fma2(wh2, h1.y, a23);
                }
                float2 p01 = unpack2(a01), p23 = unpack2(a23);
                *(float4*)&s_part[(grp2 * 225 + row) * 4] = make_float4(p01.x, p01.y, p23.x, p23.y);
            }
            __syncthreads();
            if (tid < 300) {
                float rp = s_part[uB * 4 + sB]          + s_part[(225 + uB) * 4 + sB];
                float zp = s_part[(75 + uB) * 4 + sB]   + s_part[(300 + uB) * 4 + sB];
                float np = s_part[(150 + uB) * 4 + sB]  + s_part[(375 + uB) * 4 + sB];
                float r = fsig(gr + rp + bhr);
                float z = fsig(gz + zp + bhz);
                float n = ftanh(gn2 + r * (np + bhn));
                float hold = s_h[buf * 1200 + GB * 4 + sB];
                float hn = (1.f - z) * n + z * hold;
                unsigned la = buf ? hlocal0 : hlocal1;
                #pragma unroll
                for (unsigned rk = 0; rk < 4; rk++) dst_f32(la, rk, hn);
                s_red[sB * 80 + uB] = hn * wm;
            }
            __syncthreads();
            if (wid < 4) {
                float v = s_red[wid * 80 + lane];
                if (lane < 43) v += s_red[wid * 80 + lane + 32];
                if (lane < 11) v += s_red[wid * 80 + lane + 64];
                #pragma unroll
                for (int o = 16; o > 0; o >>= 1) v += __shfl_xor_sync(0xffffffffu, v, o);
                if (lane == 0) {
                    unsigned la = smem_u32(&s_partial[buf * 16 + (int)rank * 4 + wid]);
                    dst_f32(la, 0, v);
                }
            }
            CLUSTER_SYNC();
            buf ^= 1;
        }
        if (rank == 0 && tid < 4) {
            float* pp = s_partial + (buf ^ 1) * 16;
            float sum = pp[tid] + pp[4 + tid] + pp[8 + tid] + pp[12 + tid];
            if (tmax - 1 < lenv[tid]) attn[seqv[tid] * LL + (tmax - 1)] = fsig(sum + mbb) + 0.5f;
        }
        __syncthreads();
        CLUSTER_SYNC();
    }
}

// ---------------- K3: memory = emb[text] * scale ------------------------------
__global__ void k_mem(const int* __restrict__ text, const float* __restrict__ emb)
{
    int l = blockIdx.x, b = blockIdx.y, tid = threadIdx.x;
    if (tid >= EE) return;
    float* row = g_memory + ((size_t)b * LL + l) * EE;
    int ml = g_mem_len[b];
    if (l >= ml) { row[tid] = 0.f; return; }
    int astart = g_left_len[b] - g_asp_len[b];
    int aend = g_left_len[b];
    float al = g_attn_l[b * LL + l];
    int ridx = min(max(l - astart, 0), LL - 1);
    float arv = g_attn_r[b * LL + ridx];
    float sc = (l < astart) ? al : ((l < aend) ? (al + arv) : arv);
    int id = text[b * LL + l];
    row[tid] = emb[(size_t)id * EE + tid] * sc;
}

// ---------------- K4: v_s -----------------------------------------------------
__global__ void k_vs()
{
    int b = blockIdx.x, tid = threadIdx.x;
    if (tid >= EE) return;
    float acc = 0.f;
    const float* p = g_memory + (size_t)b * LL * EE + tid;
    int ml = g_mem_len[b];
    for (int l = 0; l < ml; l++) acc += p[(size_t)l * EE];
    g_vs[b * EE + tid] = acc / (float)ml;
}

// ---------------- K5: score->softmax->v_ts->proj->mlp->dense ------------------
__global__ void __launch_bounds__(512) k_tail(
    const float* __restrict__ attn_w, const float* __restrict__ b_k,
    const float* __restrict__ proj_w, const float* __restrict__ proj_b,
    const float* __restrict__ mlp_w, const float* __restrict__ mlp_b,
    const float* __restrict__ dense_w, const float* __restrict__ dense_b,
    float* __restrict__ out)
{
    int b = blockIdx.x, tid = threadIdx.x, lane = tid & 31, wid = tid >> 5;
    __shared__ float s_aw[EE];
    __shared__ float s_sc[LL];
    __shared__ float smax[16], ssum[16];
    __shared__ float s_v[EE], s_v2[EE];
    const float* kxb = g_kx + (size_t)b * LL * EE;
    int ml = g_mem_len[b];
    if (tid < EE) s_aw[tid] = attn_w[tid];
    __syncthreads();
    float qd = g_qdot[b];
    float sc_pad = tanhf(g_kpad + qd);
    for (int l = wid; l < ml; l += 16) {
        const float* row = kxb + (size_t)l * EE;
        float acc = 0.f;
        for (int e = lane; e < EE; e += 32) acc += row[e] * s_aw[e];
        #pragma unroll
        for (int o = 16; o > 0; o >>= 1) acc += __shfl_xor_sync(0xffffffffu, acc, o);
        if (lane == 0) s_sc[l] = tanhf(acc + qd);
    }
    __syncthreads();
    float x = (tid < ml) ? s_sc[tid] : sc_pad;
    float m = x;
    #pragma unroll
    for (int o = 16; o > 0; o >>= 1) m = fmaxf(m, __shfl_xor_sync(0xffffffffu, m, o));
    if (lane == 0) smax[wid] = m;
    __syncthreads();
    float bm = smax[0];
    #pragma unroll
    for (int w = 1; w < 16; w++) bm = fmaxf(bm, smax[w]);
    float p = expf(x - bm);
    float sm = p;
    #pragma unroll
    for (int o = 16; o > 0; o >>= 1) sm += __shfl_xor_sync(0xffffffffu, sm, o);
    if (lane == 0) ssum[wid] = sm;
    __syncthreads();
    float tot = 0.f;
    #pragma unroll
    for (int w = 0; w < 16; w++) tot += ssum[w];
    s_sc[tid] = p / tot;
    __syncthreads();
    float pad_prob = expf(sc_pad - bm) / tot;
    if (tid < EE) {
        float acc = (float)(LL - ml) * pad_prob * b_k[tid];
        for (int l = 0; l < ml; l++) acc += s_sc[l] * kxb[(size_t)l * EE + tid];
        s_v[tid] = acc;
    }
    __syncthreads();
    if (tid < EE) {
        float acc = proj_b[tid];
        const float* w = proj_w + (size_t)tid * EE;
        for (int e = 0; e < EE; e++) acc += s_v[e] * w[e];
        s_v2[tid] = acc + g_vs[b * EE + tid];
    }
    __syncthreads();
    if (tid < EE) {
        float acc = mlp_b[tid];
        const float* w = mlp_w + (size_t)tid * EE;
        for (int e = 0; e < EE; e++) acc += s_v2[e] * w[e];
        s_v[tid] = tanhf(acc);
    }
    __syncthreads();
    if (wid < 3) {
        const float* w = dense_w + (size_t)wid * EE;
        float acc = 0.f;
        for (int e = lane; e < EE; e += 32) acc += s_v[e] * w[e];
        #pragma unroll
        for (int o = 16; o > 0; o >>= 1) acc += __shfl_xor_sync(0xffffffffu, acc, o);
        if (lane == 0) out[b * 3 + wid] = acc + dense_b[wid];
    }
}

extern "C" void kernel_launch(void* const* d_in, const int* in_sizes, int n_in,
                              void* d_out, int out_size)
{
    const int*   text  = (const int*)d_in[0];
    const int*   aspi  = (const int*)d_in[1];
    const int*   xl    = (const int*)d_in[2];
    const int*   xr    = (const int*)d_in[3];
    const float* emb   = (const float*)d_in[4];
    const float* emb_a = (const float*)d_in[5];
    const float* Wih_l = (const float*)d_in[6];
    const float* Whh_l = (const float*)d_in[7];
    const float* bih_l = (const float*)d_in[8];
    const float* bhh_l = (const float*)d_in[9];
    const float* Wih_r = (const float*)d_in[10];
    const float* Whh_r = (const float*)d_in[11];
    const float* bih_r = (const float*)d_in[12];
    const float* bhh_r = (const float*)d_in[13];
    const float* mlw_l = (const float*)d_in[14];
    const float* mlb_l = (const float*)d_in[15];
    const float* mlw_r = (const float*)d_in[16];
    const float* mlb_r = (const float*)d_in[17];
    const float* w_k   = (const float*)d_in[18];
    const float* b_k   = (const float*)d_in[19];
    const float* w_q   = (const float*)d_in[20];
    const float* b_q   = (const float*)d_in[21];
    const float* aw    = (const float*)d_in[22];
    const float* pw    = (const float*)d_in[23];
    const float* pb    = (const float*)d_in[24];
    const float* mw    = (const float*)d_in[25];
    const float* mb    = (const float*)d_in[26];
    const float* dw    = (const float*)d_in[27];
    const float* db    = (const float*)d_in[28];
    float* out = (float*)d_out;

    k_wpk<<<dim3(225, 8), 150>>>(Whh_l, Whh_r);
    k_init<<<BB, 512>>>(text, aspi, xl, xr, emb_a, w_q, b_q, aw, mlb_l, mlb_r);
    k_sched<<<1, 256>>>(b_k, aw);

    dim3 gx((G3 + 63) / 64, LL / 128, BB);
    k_gemm2<<<gx, 256>>>(emb, xl, Wih_l, bih_l, G3, 0, 1);
    k_gemm2<<<gx, 256>>>(emb, xr, Wih_r, bih_r, G3, 1, 2);

    k_gruC<<<BB, 512>>>(bhh_l, bhh_r, mlw_l, mlb_l, mlw_r, mlb_r);

    k_mem<<<dim3(LL, BB), 320>>>(text, emb);
    k_vs<<<BB, 320>>>();

    dim3 gk((EE + 63) / 64, LL / 128, BB);
    k_gemm2<<<gk, 256>>>(emb, (const int*)0, w_k, b_k, EE, 2, 3);

    k_tail<<<BB, 512>>>(aw, b_k, pw, pb, mw, mb, dw, db, out);
}

// round 10
// speedup vs baseline: 8.7364x; 1.4824x over previous
#include <cuda_runtime.h>
#include <cuda_bf16.h>
#include <math.h>

#define BB 128
#define LL 512
#define LAa 8
#define EE 300
#define HH 300
#define G3 900

__device__ __align__(16) int   g_mem_len[BB];
__device__ __align__(16) int   g_asp_len[BB];
__device__ __align__(16) int   g_left_len[BB];
__device__ __align__(16) int   g_right_len[BB];
__device__ __align__(16) float g_qdot[BB];
__device__ __align__(16) float g_attn_l[BB * LL];
__device__ __align__(16) float g_attn_r[BB * LL];
__device__ __align__(16) float g_xp_l[(size_t)BB * LL * G3];
__device__ __align__(16) float g_xp_r[(size_t)BB * LL * G3];
__device__ __align__(16) float g_memory[(size_t)BB * LL * EE];
__device__ __align__(16) float g_kx[(size_t)BB * LL * EE];
__device__ __align__(16) float g_vs[BB * EE];

// cluster-GRU schedule
__device__ int   g_grp_seq[64][4];
__device__ int   g_grp_len[64][4];
__device__ int   g_grp_maxlen[64];
__device__ int   g_grp_side[64];
__device__ int   g_clu_grp[32][2];
__device__ float g_kpad;
// mma A-fragment-packed weights: [(side*4+rank)*15+w][kt][lane][4] b32 (bf16x2)
__device__ __align__(16) unsigned g_Wmma[8 * 15 * 19 * 128];

__device__ __forceinline__ float sigf(float x) { return 1.0f / (1.0f + expf(-x)); }
__device__ __forceinline__ float ftanh(float x) {
    float y; asm("tanh.approx.f32 %0, %1;" : "=f"(y) : "f"(x)); return y;
}
__device__ __forceinline__ float fsig(float x) { return 0.5f * ftanh(0.5f * x) + 0.5f; }

// ---- packed f32x2 helpers (sm_103a) ----
__device__ __forceinline__ unsigned long long pack2(float lo, float hi) {
    unsigned long long r;
    asm("mov.b64 %0, {%1, %2};" : "=l"(r) : "r"(__float_as_uint(lo)), "r"(__float_as_uint(hi)));
    return r;
}
__device__ __forceinline__ unsigned long long splat2(float v) { return pack2(v, v); }
__device__ __forceinline__ unsigned long long fma2(unsigned long long a, unsigned long long b,
                                                   unsigned long long c) {
    unsigned long long d;
    asm("fma.rn.f32x2 %0, %1, %2, %3;" : "=l"(d) : "l"(a), "l"(b), "l"(c));
    return d;
}
__device__ __forceinline__ float2 unpack2(unsigned long long v) {
    unsigned lo, hi;
    asm("mov.b64 {%0, %1}, %2;" : "=r"(lo), "=r"(hi) : "l"(v));
    return make_float2(__uint_as_float(lo), __uint_as_float(hi));
}

__device__ __forceinline__ unsigned smem_u32(const void* p) {
    unsigned r;
    asm("{ .reg .u64 t; cvta.to.shared.u64 t, %1; cvt.u32.u64 %0, t; }" : "=r"(r) : "l"(p));
    return r;
}
__device__ __forceinline__ unsigned ctarank() {
    unsigned r; asm("mov.u32 %0, %%cluster_ctarank;" : "=r"(r)); return r;
}
#define CLUSTER_SYNC() do { \
    asm volatile("barrier.cluster.arrive.aligned;" ::: "memory"); \
    asm volatile("barrier.cluster.wait.aligned;" ::: "memory"); } while (0)

__device__ __forceinline__ void dst_f32(unsigned laddr, unsigned rk, float v) {
    asm volatile("{ .reg .b32 ra; mapa.shared::cluster.u32 ra, %0, %1; "
                 "st.shared::cluster.b32 [ra], %2; }"
                 :: "r"(laddr), "r"(rk), "r"(__float_as_uint(v)) : "memory");
}

#define MMA16816(c0,c1,c2,c3,a0,a1,a2,a3,b0,b1) \
    asm volatile("mma.sync.aligned.m16n8k16.row.col.f32.bf16.bf16.f32 " \
                 "{%0,%1,%2,%3}, {%4,%5,%6,%7}, {%8,%9}, {%0,%1,%2,%3};" \
                 : "+f"(c0), "+f"(c1), "+f"(c2), "+f"(c3) \
                 : "r"(a0), "r"(a1), "r"(a2), "r"(a3), "r"(b0), "r"(b1))

// ---------------- K_wpk2: pack W_hh into mma A-fragment layout ----------------
// warp w owns packed rows [16w,16w+16); row r<225 -> gate G=(r/75)*300+rank*75+r%75
__global__ void k_wpk2(const float* __restrict__ Whh_l, const float* __restrict__ Whh_r)
{
    int tid = threadIdx.x;                 // 128
    int j = tid >> 5, l = tid & 31;
    int gid = l >> 2, tig = l & 3;
    int wkt = blockIdx.x;                  // 0..284
    int w = wkt / 19, kt = wkt % 19;
    int sr = blockIdx.y;                   // 0..7
    int side = sr >> 2, rank = sr & 3;
    const float* W = side ? Whh_r : Whh_l;

    int rl = gid + ((j & 1) ? 8 : 0);
    int k  = kt * 16 + tig * 2 + ((j >= 2) ? 8 : 0);
    int r  = 16 * w + rl;
    float lo = 0.f, hi = 0.f;
    if (r < 225) {
        int G = (r / 75) * 300 + rank * 75 + (r % 75);
        if (k < 300)     lo = W[(size_t)G * HH + k];
        if (k + 1 < 300) hi = W[(size_t)G * HH + k + 1];
    }
    __nv_bfloat162 p = __floats2bfloat162_rn(lo, hi);
    g_Wmma[(size_t)((sr * 15 + w) * 19 + kt) * 128 + l * 4 + j] = *(unsigned*)&p;
}

// ---------------- K0: lengths, attn defaults, aspect mean -> qdot -------------
__global__ void k_init(const int* __restrict__ text, const int* __restrict__ aspi,
                       const int* __restrict__ xl, const int* __restrict__ xr,
                       const float* __restrict__ emb_aspect,
                       const float* __restrict__ w_q, const float* __restrict__ b_q,
                       const float* __restrict__ attn_w,
                       const float* __restrict__ mlp_l_b, const float* __restrict__ mlp_r_b)
{
    int b = blockIdx.x, tid = threadIdx.x;
    int ml = __syncthreads_count(text[b * LL + tid] != 0);
    int ll = __syncthreads_count(xl[b * LL + tid] != 0);
    int rl = __syncthreads_count(xr[b * LL + tid] != 0);
    int al = __syncthreads_count((tid < LAa) && (aspi[b * LAa + tid] != 0));
    if (tid == 0) { g_mem_len[b] = ml; g_left_len[b] = ll; g_right_len[b] = rl; g_asp_len[b] = al; }
    g_attn_l[b * LL + tid] = sigf(mlp_l_b[0]) + 0.5f;
    g_attn_r[b * LL + tid] = sigf(mlp_r_b[0]) + 0.5f;

    __shared__ float s_asp[EE];
    __shared__ float sred[16];
    if (tid < EE) {
        float acc = 0.f;
        #pragma unroll
        for (int a = 0; a < LAa; a++)
            if (a < al) acc += emb_aspect[(size_t)aspi[b * LAa + a] * EE + tid];
        s_asp[tid] = acc / (float)al;
    }
    __syncthreads();
    float val = 0.f;
    if (tid < EE) {
        float acc = b_q[tid];
        const float* wq = w_q + (size_t)tid * EE;
        for (int e = 0; e < EE; e++) acc += s_asp[e] * wq[e];
        val = acc * attn_w[EE + tid];
    }
    #pragma unroll
    for (int o = 16; o > 0; o >>= 1) val += __shfl_xor_sync(0xffffffffu, val, o);
    if ((tid & 31) == 0) sred[tid >> 5] = val;
    __syncthreads();
    if (tid == 0) {
        float s = 0.f;
        #pragma unroll
        for (int w = 0; w < 16; w++) s += sred[w];
        g_qdot[b] = s;
    }
}

// ---------------- K_sched: groups of 4 per side, snake over 32 clusters -------
__global__ void k_sched(const float* __restrict__ b_k, const float* __restrict__ attn_w)
{
    __shared__ float sred[256];
    int i = threadIdx.x;  // 256 threads, 1 block
    float p = 0.f;
    for (int e = i; e < EE; e += 256) p += b_k[e] * attn_w[e];
    sred[i] = p;
    __syncthreads();
    if (i == 0) { float s = 0.f; for (int m = 0; m < 256; m++) s += sred[m]; g_kpad = s; }

    int side = i >> 7, j = i & 127;
    const int* lens = side ? g_right_len : g_left_len;
    int lj = lens[j], r = 0;
    for (int m = 0; m < BB; m++) {
        int lm = lens[m];
        r += (lm > lj) || (lm == lj && m < j);
    }
    int g = side * 32 + (r >> 2);
    g_grp_seq[g][r & 3] = j;
    g_grp_len[g][r & 3] = lj;
    if ((r & 3) == 0) { g_grp_maxlen[g] = lj; g_grp_side[g] = side; }
    __syncthreads();
    if (i < 64) {
        int ml = g_grp_maxlen[i]; int r2 = 0;
        for (int m = 0; m < 64; m++) {
            int lm = g_grp_maxlen[m];
            r2 += (lm > ml) || (lm == ml && m < i);
        }
        int cl = (r2 < 32) ? r2 : 63 - r2;
        g_clu_grp[cl][(r2 < 32) ? 0 : 1] = i;
    }
}

// ---------------- K1: GEMM — 128x64 tile, 8x4 per-thread, FFMA2 (R8) ----------
__global__ void __launch_bounds__(256) k_gemm2(
    const float* __restrict__ Aext, const int* __restrict__ ids,
    const float* __restrict__ W, const float* __restrict__ bias,
    int N, int dst_sel, int limit_sel)
{
    const int K = EE;
    int b = blockIdx.z, m0 = blockIdx.y * 128, n0 = blockIdx.x * 64;
    int lim = (limit_sel == 1) ? g_left_len[b] : (limit_sel == 2) ? g_right_len[b]
            : (limit_sel == 3) ? g_mem_len[b] : LL;
    if (m0 >= lim) return;

    float* C = (dst_sel == 0) ? g_xp_l : (dst_sel == 1) ? g_xp_r : g_kx;
    float* Cb = C + (size_t)b * LL * N;
    const int* bids = ids ? (ids + (size_t)b * LL) : (const int*)0;

    __shared__ __align__(16) float As[16][128];
    __shared__ __align__(16) float Bs[16][64];

    int tid = threadIdx.x;
    int tx = tid & 15, ty = tid >> 4;
    int ar = tid >> 1, ac = (tid & 1) * 8;
    int br = tid >> 2, bc = (tid & 3) * 4;

    int gm = m0 + ar;
    const float* arow;
    if (bids) arow = Aext + (size_t)bids[gm] * K;
    else      arow = g_memory + ((size_t)b * LL + gm) * K;
    int gn = n0 + br;
    const float* brow = (gn < N) ? (W + (size_t)gn * K) : (const float*)0;

    unsigned long long acc01[8], acc23[8];
    #pragma unroll
    for (int i = 0; i < 8; i++) { acc01[i] = 0ull; acc23[i] = 0ull; }

    for (int k0 = 0; k0 < K; k0 += 16) {
        float4 av0 = make_float4(0.f, 0.f, 0.f, 0.f);
        float4 av1 = make_float4(0.f, 0.f, 0.f, 0.f);
        float4 bv  = make_float4(0.f, 0.f, 0.f, 0.f);
        if (k0 + ac < K)     av0 = *(const float4*)(arow + k0 + ac);
        if (k0 + ac + 4 < K) av1 = *(const float4*)(arow + k0 + ac + 4);
        if (brow && (k0 + bc < K)) bv = *(const float4*)(brow + k0 + bc);
        __syncthreads();
        As[ac + 0][ar] = av0.x; As[ac + 1][ar] = av0.y;
        As[ac + 2][ar] = av0.z; As[ac + 3][ar] = av0.w;
        As[ac + 4][ar] = av1.x; As[ac + 5][ar] = av1.y;
        As[ac + 6][ar] = av1.z; As[ac + 7][ar] = av1.w;
        Bs[bc + 0][br] = bv.x; Bs[bc + 1][br] = bv.y;
        Bs[bc + 2][br] = bv.z; Bs[bc + 3][br] = bv.w;
        __syncthreads();
        #pragma unroll
        for (int kk = 0; kk < 16; kk++) {
            float4 a0 = *(const float4*)&As[kk][ty * 8];
            float4 a1 = *(const float4*)&As[kk][ty * 8 + 4];
            ulonglong2 bb2 = *(const ulonglong2*)&Bs[kk][tx * 4];
            float av[8] = {a0.x, a0.y, a0.z, a0.w, a1.x, a1.y, a1.z, a1.w};
            #pragma unroll
            for (int i = 0; i < 8; i++) {
                unsigned long long as = splat2(av[i]);
                acc01[i] = fma2(as, bb2.x, acc01[i]);
                acc23[i] = fma2(as, bb2.y, acc23[i]);
            }
        }
    }
    #pragma unroll
    for (int i = 0; i < 8; i++) {
        int om = m0 + ty * 8 + i;
        float2 p01 = unpack2(acc01[i]);
        float2 p23 = unpack2(acc23[i]);
        float vj[4] = {p01.x, p01.y, p23.x, p23.y};
        #pragma unroll
        for (int j = 0; j < 4; j++) {
            int on = n0 + tx * 4 + j;
            if (on < N) Cb[(size_t)om * N + on] = vj[j] + bias[on];
        }
    }
}

// ---------------- K2: cluster-4 GRU, tensor-core GEMV (HMMA m16n8k16) ---------
// 32 clusters x 4 CTAs; CTA owns gate rows r=0..224 (G=(r/75)*300+rank*75+r%75).
// Warps 0..14: one 16-row tile each, 19 k-tiles chained, A frags in registers.
__global__ void __launch_bounds__(512, 1) __cluster_dims__(4, 1, 1)
k_gruT(const float* __restrict__ bhh_l, const float* __restrict__ bhh_r,
       const float* __restrict__ mlpw_l, const float* __restrict__ mlpb_l,
       const float* __restrict__ mlpw_r, const float* __restrict__ mlpb_r)
{
    __shared__ __align__(16) float s_h[2][4][304];     // fp32 h, double-buffered
    __shared__ __align__(16) unsigned hb[8 * 156];     // bf16x2 h, B-frag layout
    __shared__ __align__(16) float s_gate[240][4];
    __shared__ float s_red[320];
    __shared__ float s_partial[32];

    int tid = threadIdx.x, lane = tid & 31, wid = tid >> 5;
    int gid = lane >> 2, tig = lane & 3;
    unsigned rank = ctarank();
    int c = blockIdx.x >> 2;

    for (int gi = 0; gi < 2; gi++) {
        int grp  = g_clu_grp[c][gi];
        int side = g_grp_side[grp];
        int tmax = g_grp_maxlen[grp];
        const float* bhh  = side ? bhh_r : bhh_l;
        const float* mlpw = side ? mlpw_r : mlpw_l;
        float mbb = side ? mlpb_r[0] : mlpb_l[0];
        const float* xp = side ? g_xp_r : g_xp_l;
        float* attn = side ? g_attn_r : g_attn_l;
        int seqv[4], lenv[4];
        #pragma unroll
        for (int s = 0; s < 4; s++) { seqv[s] = g_grp_seq[grp][s]; lenv[s] = g_grp_len[grp][s]; }

        for (int i = tid; i < 2 * 4 * 304; i += 512) ((float*)s_h)[i] = 0.f;
        for (int i = tid; i < 8 * 156; i += 512) hb[i] = 0u;

        // preload A fragments (weights) for this side
        unsigned a[19][4];
        if (wid < 15) {
            const uint4* src = (const uint4*)g_Wmma
                             + (size_t)(((side * 4 + (int)rank) * 15 + wid) * 19) * 32 + lane;
            #pragma unroll
            for (int kt = 0; kt < 19; kt++) {
                uint4 v = src[kt * 32];
                a[kt][0] = v.x; a[kt][1] = v.y; a[kt][2] = v.z; a[kt][3] = v.w;
            }
        }

        int sB = tid / 75, uB = tid % 75, GB = (int)rank * 75 + uB;
        float bhr = 0.f, bhz = 0.f, bhn = 0.f, wm = 0.f, h_reg = 0.f;
        const float* xpb = 0;
        if (tid < 300) {
            bhr = bhh[GB]; bhz = bhh[300 + GB]; bhn = bhh[600 + GB]; wm = mlpw[GB];
            xpb = xp + (size_t)seqv[sB] * LL * G3;
        }
        unsigned hl0 = 0, hl1 = 0;
        if (tid < 300) {
            hl0 = smem_u32(&s_h[0][sB][GB]);
            hl1 = smem_u32(&s_h[1][sB][GB]);
        }
        __syncthreads();
        CLUSTER_SYNC();

        int buf = 0;
        for (int t = 0; t < tmax; t++) {
            if (t > 0 && rank == 0 && tid < 4) {
                float* pp = s_partial + (buf ^ 1) * 16;
                float sum = pp[tid] + pp[4 + tid] + pp[8 + tid] + pp[12 + tid];
                if (t - 1 < lenv[tid]) attn[seqv[tid] * LL + (t - 1)] = fsig(sum + mbb) + 0.5f;
            }
            float gr = 0.f, gz = 0.f, gn2 = 0.f;
            if (tid < 300) {
                const float* xr = xpb + (size_t)t * G3;
                gr = xr[GB]; gz = xr[300 + GB]; gn2 = xr[600 + GB];
            }
            // stage 1: fp32 h -> bf16 B-layout
            if (tid < 300) {
                __nv_bfloat16* hh = (__nv_bfloat16*)hb;
                #pragma unroll
                for (int s = 0; s < 4; s++)
                    hh[s * 312 + tid] = __float2bfloat16(s_h[buf][s][tid]);
            }
            __syncthreads();
            // stage 2: tensor GEMV
            if (wid < 15) {
                float c0 = 0.f, c1 = 0.f, c2 = 0.f, c3 = 0.f;
                float d0 = 0.f, d1 = 0.f, d2 = 0.f, d3 = 0.f;
                #pragma unroll
                for (int kt = 0; kt < 19; kt += 2) {
                    unsigned b0 = hb[gid * 156 + kt * 8 + tig];
                    unsigned b1 = hb[gid * 156 + kt * 8 + tig + 4];
                    MMA16816(c0, c1, c2, c3, a[kt][0], a[kt][1], a[kt][2], a[kt][3], b0, b1);
                    if (kt + 1 < 19) {
                        unsigned e0 = hb[gid * 156 + (kt + 1) * 8 + tig];
                        unsigned e1 = hb[gid * 156 + (kt + 1) * 8 + tig + 4];
                        MMA16816(d0, d1, d2, d3, a[kt+1][0], a[kt+1][1], a[kt+1][2], a[kt+1][3], e0, e1);
                    }
                }
                c0 += d0; c1 += d1; c2 += d2; c3 += d3;
                if (tig < 2) {
                    int r0 = wid * 16 + gid;
                    *(float2*)&s_gate[r0][2 * tig]     = make_float2(c0, c1);
                    *(float2*)&s_gate[r0 + 8][2 * tig] = make_float2(c2, c3);
                }
            }
            __syncthreads();
            // stage 3: gate math + h broadcast
            if (tid < 300) {
                float rp = s_gate[uB][sB];
                float zp = s_gate[75 + uB][sB];
                float np = s_gate[150 + uB][sB];
                float r = fsig(gr + rp + bhr);
                float z = fsig(gz + zp + bhz);
                float n = ftanh(gn2 + r * (np + bhn));
                h_reg = (1.f - z) * n + z * h_reg;
                unsigned la = buf ? hl0 : hl1;
                #pragma unroll
                for (unsigned rk = 0; rk < 4; rk++) dst_f32(la, rk, h_reg);
                s_red[sB * 80 + uB] = h_reg * wm;
            }
            __syncthreads();
            if (wid < 4) {
                float v = s_red[wid * 80 + lane];
                if (lane < 43) v += s_red[wid * 80 + lane + 32];
                if (lane < 11) v += s_red[wid * 80 + lane + 64];
                #pragma unroll
                for (int o = 16; o > 0; o >>= 1) v += __shfl_xor_sync(0xffffffffu, v, o);
                if (lane == 0) {
                    unsigned la = smem_u32(&s_partial[buf * 16 + (int)rank * 4 + wid]);
                    dst_f32(la, 0, v);
                }
            }
            CLUSTER_SYNC();
            buf ^= 1;
        }
        if (rank == 0 && tid < 4) {
            float* pp = s_partial + (buf ^ 1) * 16;
            float sum = pp[tid] + pp[4 + tid] + pp[8 + tid] + pp[12 + tid];
            if (tmax - 1 < lenv[tid]) attn[seqv[tid] * LL + (tmax - 1)] = fsig(sum + mbb) + 0.5f;
        }
        __syncthreads();
        CLUSTER_SYNC();
    }
}

// ---------------- K3: memory = emb[text] * scale ------------------------------
__global__ void k_mem(const int* __restrict__ text, const float* __restrict__ emb)
{
    int l = blockIdx.x, b = blockIdx.y, tid = threadIdx.x;
    if (tid >= EE) return;
    float* row = g_memory + ((size_t)b * LL + l) * EE;
    int ml = g_mem_len[b];
    if (l >= ml) { row[tid] = 0.f; return; }
    int astart = g_left_len[b] - g_asp_len[b];
    int aend = g_left_len[b];
    float al = g_attn_l[b * LL + l];
    int ridx = min(max(l - astart, 0), LL - 1);
    float arv = g_attn_r[b * LL + ridx];
    float sc = (l < astart) ? al : ((l < aend) ? (al + arv) : arv);
    int id = text[b * LL + l];
    row[tid] = emb[(size_t)id * EE + tid] * sc;
}

// ---------------- K4: v_s -----------------------------------------------------
__global__ void k_vs()
{
    int b = blockIdx.x, tid = threadIdx.x;
    if (tid >= EE) return;
    float acc = 0.f;
    const float* p = g_memory + (size_t)b * LL * EE + tid;
    int ml = g_mem_len[b];
    for (int l = 0; l < ml; l++) acc += p[(size_t)l * EE];
    g_vs[b * EE + tid] = acc / (float)ml;
}

// ---------------- K5: score->softmax->v_ts->proj->mlp->dense ------------------
__global__ void __launch_bounds__(512) k_tail(
    const float* __restrict__ attn_w, const float* __restrict__ b_k,
    const float* __restrict__ proj_w, const float* __restrict__ proj_b,
    const float* __restrict__ mlp_w, const float* __restrict__ mlp_b,
    const float* __restrict__ dense_w, const float* __restrict__ dense_b,
    float* __restrict__ out)
{
    int b = blockIdx.x, tid = threadIdx.x, lane = tid & 31, wid = tid >> 5;
    __shared__ float s_aw[EE];
    __shared__ float s_sc[LL];
    __shared__ float smax[16], ssum[16];
    __shared__ float s_v[EE], s_v2[EE];
    const float* kxb = g_kx + (size_t)b * LL * EE;
    int ml = g_mem_len[b];
    if (tid < EE) s_aw[tid] = attn_w[tid];
    __syncthreads();
    float qd = g_qdot[b];
    float sc_pad = tanhf(g_kpad + qd);
    for (int l = wid; l < ml; l += 16) {
        const float* row = kxb + (size_t)l * EE;
        float acc = 0.f;
        for (int e = lane; e < EE; e += 32) acc += row[e] * s_aw[e];
        #pragma unroll
        for (int o = 16; o > 0; o >>= 1) acc += __shfl_xor_sync(0xffffffffu, acc, o);
        if (lane == 0) s_sc[l] = tanhf(acc + qd);
    }
    __syncthreads();
    float x = (tid < ml) ? s_sc[tid] : sc_pad;
    float m = x;
    #pragma unroll
    for (int o = 16; o > 0; o >>= 1) m = fmaxf(m, __shfl_xor_sync(0xffffffffu, m, o));
    if (lane == 0) smax[wid] = m;
    __syncthreads();
    float bm = smax[0];
    #pragma unroll
    for (int w = 1; w < 16; w++) bm = fmaxf(bm, smax[w]);
    float p = expf(x - bm);
    float sm = p;
    #pragma unroll
    for (int o = 16; o > 0; o >>= 1) sm += __shfl_xor_sync(0xffffffffu, sm, o);
    if (lane == 0) ssum[wid] = sm;
    __syncthreads();
    float tot = 0.f;
    #pragma unroll
    for (int w = 0; w < 16; w++) tot += ssum[w];
    s_sc[tid] = p / tot;
    __syncthreads();
    float pad_prob = expf(sc_pad - bm) / tot;
    if (tid < EE) {
        float acc = (float)(LL - ml) * pad_prob * b_k[tid];
        for (int l = 0; l < ml; l++) acc += s_sc[l] * kxb[(size_t)l * EE + tid];
        s_v[tid] = acc;
    }
    __syncthreads();
    if (tid < EE) {
        float acc = proj_b[tid];
        const float* w = proj_w + (size_t)tid * EE;
        for (int e = 0; e < EE; e++) acc += s_v[e] * w[e];
        s_v2[tid] = acc + g_vs[b * EE + tid];
    }
    __syncthreads();
    if (tid < EE) {
        float acc = mlp_b[tid];
        const float* w = mlp_w + (size_t)tid * EE;
        for (int e = 0; e < EE; e++) acc += s_v2[e] * w[e];
        s_v[tid] = tanhf(acc);
    }
    __syncthreads();
    if (wid < 3) {
        const float* w = dense_w + (size_t)wid * EE;
        float acc = 0.f;
        for (int e = lane; e < EE; e += 32) acc += s_v[e] * w[e];
        #pragma unroll
        for (int o = 16; o > 0; o >>= 1) acc += __shfl_xor_sync(0xffffffffu, acc, o);
        if (lane == 0) out[b * 3 + wid] = acc + dense_b[wid];
    }
}

extern "C" void kernel_launch(void* const* d_in, const int* in_sizes, int n_in,
                              void* d_out, int out_size)
{
    const int*   text  = (const int*)d_in[0];
    const int*   aspi  = (const int*)d_in[1];
    const int*   xl    = (const int*)d_in[2];
    const int*   xr    = (const int*)d_in[3];
    const float* emb   = (const float*)d_in[4];
    const float* emb_a = (const float*)d_in[5];
    const float* Wih_l = (const float*)d_in[6];
    const float* Whh_l = (const float*)d_in[7];
    const float* bih_l = (const float*)d_in[8];
    const float* bhh_l = (const float*)d_in[9];
    const float* Wih_r = (const float*)d_in[10];
    const float* Whh_r = (const float*)d_in[11];
    const float* bih_r = (const float*)d_in[12];
    const float* bhh_r = (const float*)d_in[13];
    const float* mlw_l = (const float*)d_in[14];
    const float* mlb_l = (const float*)d_in[15];
    const float* mlw_r = (const float*)d_in[16];
    const float* mlb_r = (const float*)d_in[17];
    const float* w_k   = (const float*)d_in[18];
    const float* b_k   = (const float*)d_in[19];
    const float* w_q   = (const float*)d_in[20];
    const float* b_q   = (const float*)d_in[21];
    const float* aw    = (const float*)d_in[22];
    const float* pw    = (const float*)d_in[23];
    const float* pb    = (const float*)d_in[24];
    const float* mw    = (const float*)d_in[25];
    const float* mb    = (const float*)d_in[26];
    const float* dw    = (const float*)d_in[27];
    const float* db    = (const float*)d_in[28];
    float* out = (float*)d_out;

    k_wpk2<<<dim3(285, 8), 128>>>(Whh_l, Whh_r);
    k_init<<<BB, 512>>>(text, aspi, xl, xr, emb_a, w_q, b_q, aw, mlb_l, mlb_r);
    k_sched<<<1, 256>>>(b_k, aw);

    dim3 gx((G3 + 63) / 64, LL / 128, BB);
    k_gemm2<<<gx, 256>>>(emb, xl, Wih_l, bih_l, G3, 0, 1);
    k_gemm2<<<gx, 256>>>(emb, xr, Wih_r, bih_r, G3, 1, 2);

    k_gruT<<<BB, 512>>>(bhh_l, bhh_r, mlw_l, mlb_l, mlw_r, mlb_r);

    k_mem<<<dim3(LL, BB), 320>>>(text, emb);
    k_vs<<<BB, 320>>>();

    dim3 gk((EE + 63) / 64, LL / 128, BB);
    k_gemm2<<<gk, 256>>>(emb, (const int*)0, w_k, b_k, EE, 2, 3);

    k_tail<<<BB, 512>>>(aw, b_k, pw, pb, mw, mb, dw, db, out);
}